// round 14
// baseline (speedup 1.0000x reference)
#include <cuda_runtime.h>
#include <cuda_bf16.h>
#include <cuda_fp16.h>
#include <cstdint>

// Problem constants
#define BATCH   4
#define SEQ     1024
#define EMB     1024
#define HEADS   16
#define HDIM    64
#define MROWS   (BATCH * SEQ)      // 4096

// ---------------- scratch (16B-aligned for cp.async) ----------------
__device__ __align__(256) __nv_bfloat16 g_Xhi[MROWS * EMB];
__device__ __align__(256) __nv_bfloat16 g_Xlo[MROWS * EMB];
// Q/K in per-head layout [B, H, S, HDIM], bf16 hi/lo; V fp16 hi/lo
__device__ __align__(256) __nv_bfloat16 g_Qhi[MROWS * EMB];
__device__ __align__(256) __nv_bfloat16 g_Qlo[MROWS * EMB];
__device__ __align__(256) __nv_bfloat16 g_Khi[MROWS * EMB];
__device__ __align__(256) __nv_bfloat16 g_Klo[MROWS * EMB];
__device__ __align__(256) __half       g_Vhi[MROWS * EMB];
__device__ __align__(256) __half       g_Vlo[MROWS * EMB];
// Z single fp16 ([B,H,S,Dh] flat = [MROWS, EMB] row-major view)
__device__ __align__(256) __half       g_Z[MROWS * EMB];
// wq,wk,wv transposed [N,K] bf16 hi/lo; wo transposed [N,K] fp16 hi/lo
__device__ __align__(256) __nv_bfloat16 g_Whi[3 * EMB * EMB];
__device__ __align__(256) __nv_bfloat16 g_Wlo[3 * EMB * EMB];
__device__ __align__(256) __half       g_WOhi[EMB * EMB];
__device__ __align__(256) __half       g_WOlo[EMB * EMB];

// ================= PTX helpers (sm_80+ subset only) =============
__device__ __forceinline__ uint32_t smem_u32(const void* p) {
    uint32_t a;
    asm("{ .reg .u64 t; cvta.to.shared.u64 t, %1; cvt.u32.u64 %0, t; }" : "=r"(a) : "l"(p));
    return a;
}

__device__ __forceinline__ void cp_async16(uint32_t saddr, const void* gaddr) {
    asm volatile("cp.async.cg.shared.global [%0], [%1], 16;" :: "r"(saddr), "l"(gaddr));
}
#define CP_COMMIT()  asm volatile("cp.async.commit_group;" ::: "memory")
template <int N>
__device__ __forceinline__ void cp_wait() {
    asm volatile("cp.async.wait_group %0;" :: "n"(N) : "memory");
}

#define BAR_ARRIVE(id, cnt) \
    asm volatile("bar.arrive %0, %1;" :: "r"((int)(id)), "r"((int)(cnt)) : "memory")
#define BAR_SYNC_N(id, cnt) \
    asm volatile("bar.sync %0, %1;" :: "r"((int)(id)), "r"((int)(cnt)) : "memory")

__device__ __forceinline__ void ldmatrix_x4(uint32_t (&r)[4], uint32_t addr) {
    asm volatile("ldmatrix.sync.aligned.m8n8.x4.shared.b16 {%0,%1,%2,%3}, [%4];"
                 : "=r"(r[0]), "=r"(r[1]), "=r"(r[2]), "=r"(r[3]) : "r"(addr));
}
__device__ __forceinline__ void ldmatrix_x4_trans(uint32_t (&r)[4], uint32_t addr) {
    asm volatile("ldmatrix.sync.aligned.m8n8.x4.trans.shared.b16 {%0,%1,%2,%3}, [%4];"
                 : "=r"(r[0]), "=r"(r[1]), "=r"(r[2]), "=r"(r[3]) : "r"(addr));
}

__device__ __forceinline__ void mma_16816(float (&d)[4], const uint32_t (&a)[4],
                                          uint32_t b0, uint32_t b1) {
    asm volatile(
        "mma.sync.aligned.m16n8k16.row.col.f32.bf16.bf16.f32 "
        "{%0,%1,%2,%3}, {%4,%5,%6,%7}, {%8,%9}, {%0,%1,%2,%3};"
        : "+f"(d[0]), "+f"(d[1]), "+f"(d[2]), "+f"(d[3])
        : "r"(a[0]), "r"(a[1]), "r"(a[2]), "r"(a[3]), "r"(b0), "r"(b1));
}
__device__ __forceinline__ void mma_16816_f16(float (&d)[4], const uint32_t (&a)[4],
                                              uint32_t b0, uint32_t b1) {
    asm volatile(
        "mma.sync.aligned.m16n8k16.row.col.f32.f16.f16.f32 "
        "{%0,%1,%2,%3}, {%4,%5,%6,%7}, {%8,%9}, {%0,%1,%2,%3};"
        : "+f"(d[0]), "+f"(d[1]), "+f"(d[2]), "+f"(d[3])
        : "r"(a[0]), "r"(a[1]), "r"(a[2]), "r"(a[3]), "r"(b0), "r"(b1));
}

// fp32 pair -> packed bf16x2 hi + lo
__device__ __forceinline__ void split2(float x, float y, uint32_t& hi, uint32_t& lo) {
    __nv_bfloat16 hx = __float2bfloat16(x);
    __nv_bfloat16 hy = __float2bfloat16(y);
    __nv_bfloat16 lx = __float2bfloat16(x - __bfloat162float(hx));
    __nv_bfloat16 ly = __float2bfloat16(y - __bfloat162float(hy));
    __nv_bfloat162 hp(hx, hy), lp(lx, ly);
    hi = *(uint32_t*)&hp;
    lo = *(uint32_t*)&lp;
}
// fp32 pair -> packed fp16x2 hi + lo
__device__ __forceinline__ void split2h(float x, float y, uint32_t& hi, uint32_t& lo) {
    __half hx = __float2half_rn(x);
    __half hy = __float2half_rn(y);
    __half lx = __float2half_rn(x - __half2float(hx));
    __half ly = __float2half_rn(y - __half2float(hy));
    __half2 hp(hx, hy), lp(lx, ly);
    hi = *(uint32_t*)&hp;
    lo = *(uint32_t*)&lp;
}
__device__ __forceinline__ uint32_t packh2(float x, float y) {
    __half2 h = __floats2half2_rn(x, y);
    return *(uint32_t*)&h;
}

// ================= conversion kernels =================
__global__ __launch_bounds__(256) void cvt_split_kernel(
    const float* __restrict__ src, __nv_bfloat16* __restrict__ hi,
    __nv_bfloat16* __restrict__ lo)
{
    int i = blockIdx.x * blockDim.x + threadIdx.x;     // one float4 each
    float4 v = ((const float4*)src)[i];
    uint32_t h0, l0, h1, l1;
    split2(v.x, v.y, h0, l0);
    split2(v.z, v.w, h1, l1);
    ((uint2*)hi)[i] = make_uint2(h0, h1);
    ((uint2*)lo)[i] = make_uint2(l0, l1);
}

// W [K,N] fp32 -> WT [N,K] hi/lo (transpose+split). z<3: bf16; z==3: fp16.
__global__ __launch_bounds__(256) void cvt_splitT_kernel(
    const float* __restrict__ w0, const float* __restrict__ w1,
    const float* __restrict__ w2, const float* __restrict__ w3)
{
    __shared__ float t[32][33];
    const int z = blockIdx.z;
    const float* W = (z == 0) ? w0 : (z == 1) ? w1 : (z == 2) ? w2 : w3;
    const int bx = blockIdx.x * 32;   // N base
    const int by = blockIdx.y * 32;   // K base
    const int tx = threadIdx.x & 31;
    const int ty = threadIdx.x >> 5;  // 0..7
    for (int i = ty; i < 32; i += 8)
        t[i][tx] = W[(size_t)(by + i) * EMB + bx + tx];
    __syncthreads();
    if (z < 3) {
        __nv_bfloat16* hiT = g_Whi + (size_t)z * EMB * EMB;
        __nv_bfloat16* loT = g_Wlo + (size_t)z * EMB * EMB;
        for (int i = ty; i < 32; i += 8) {
            float v = t[tx][i];
            __nv_bfloat16 h = __float2bfloat16(v);
            __nv_bfloat16 l = __float2bfloat16(v - __bfloat162float(h));
            hiT[(size_t)(bx + i) * EMB + by + tx] = h;
            loT[(size_t)(bx + i) * EMB + by + tx] = l;
        }
    } else {
        for (int i = ty; i < 32; i += 8) {
            float v = t[tx][i];
            __half h = __float2half_rn(v);
            __half l = __float2half_rn(v - __half2float(h));
            g_WOhi[(size_t)(bx + i) * EMB + by + tx] = h;
            g_WOlo[(size_t)(bx + i) * EMB + by + tx] = l;
        }
    }
}

// ========== HMMA bf16x3 QKV GEMM — 256x128 tile, 512 thr, 3-stage ==========
#define BK          32
#define NCHUNK      (EMB / BK)              // 32
#define SA          40                       // smem row stride (elems)
#define QA_BYTES    (256 * SA * 2)          // 20480 per A split
#define QB_BYTES    (128 * SA * 2)          // 10240 per B split
#define QSTAGE      (2 * QA_BYTES + 2 * QB_BYTES)   // 61440
#define GEMM_SMEM   (3 * QSTAGE)            // 184320

// Q pre-scale: 1/16^0.25 * log2(e)  (softmax done in exp2 domain)
#define QSCALE (0.5f * 1.4426950408889634f)

__device__ __forceinline__ void load_stage_qkv(
    uint32_t smb, const __nv_bfloat16* __restrict__ Bh, const __nv_bfloat16* __restrict__ Bl,
    int mbase, int nbase, int k0, int stage, int tid)
{
    const uint32_t sbase = smb + stage * QSTAGE;
    // A: 256 rows x 32 cols, hi+lo: 1024 chunks each, 512 threads x 2
#pragma unroll
    for (int i = 0; i < 2; ++i) {
        int idx = tid + i * 512;
        int r = idx >> 2, seg = idx & 3;
        uint32_t so = (r * SA + seg * 8) * 2;
        const size_t g = (size_t)(mbase + r) * EMB + k0 + seg * 8;
        cp_async16(sbase + so,            g_Xhi + g);
        cp_async16(sbase + QA_BYTES + so, g_Xlo + g);
    }
    // B: 128 rows x 32 cols, hi+lo: 512 chunks each, 1 per thread
    {
        int r = tid >> 2, seg = tid & 3;
        uint32_t so = (r * SA + seg * 8) * 2;
        const size_t g = (size_t)(nbase + r) * EMB + k0 + seg * 8;
        cp_async16(sbase + 2 * QA_BYTES + so,            Bh + g);
        cp_async16(sbase + 2 * QA_BYTES + QB_BYTES + so, Bl + g);
    }
}

// mode 0: Q (bf16 split, xQSCALE); mode 1: K (bf16 split); mode 2: V (fp16 split)
__global__ __launch_bounds__(512, 1)
void qkv_mma_kernel(const float* __restrict__ bq, const float* __restrict__ bk,
                    const float* __restrict__ bv)
{
    extern __shared__ char sm[];
    const uint32_t smb = smem_u32(sm);
    const int tid  = threadIdx.x;          // 512 threads, 16 warps
    const int wid  = tid >> 5;
    const int lane = tid & 31;
    const int mbase = blockIdx.y * 256;
    const int nbase = blockIdx.x * 128;
    const int mode = blockIdx.z;

    const __nv_bfloat16* Bh = g_Whi + (size_t)mode * EMB * EMB;
    const __nv_bfloat16* Bl = g_Wlo + (size_t)mode * EMB * EMB;
    const float* bias = (mode == 0) ? bq : (mode == 1) ? bk : bv;

    const int wm = (wid & 3) * 64;        // 4 warps along M (256)
    const int wn = (wid >> 2) * 32;       // 4 warps along N (128)

    float acc[4][4][4];
#pragma unroll
    for (int mi = 0; mi < 4; ++mi)
#pragma unroll
        for (int ni = 0; ni < 4; ++ni)
#pragma unroll
            for (int e = 0; e < 4; ++e) acc[mi][ni][e] = 0.f;

    const int a_row = (lane & 15);
    const int a_koff = (lane >> 4) * 8;
    const int b_row = (lane & 7) + ((lane >> 4) * 8);
    const int b_koff = ((lane >> 3) & 1) * 8;

    // 3-stage prologue: chunks 0, 1
    load_stage_qkv(smb, Bh, Bl, mbase, nbase, 0, 0, tid);
    CP_COMMIT();
    load_stage_qkv(smb, Bh, Bl, mbase, nbase, BK, 1, tid);
    CP_COMMIT();

    for (int ck = 0; ck < NCHUNK; ++ck) {
        const int buf = ck % 3;
        if (ck + 1 < NCHUNK) cp_wait<1>();   // chunk ck done, ck+1 in flight
        else                 cp_wait<0>();   // last chunk done
        __syncthreads();
        if (ck + 2 < NCHUNK) {
            load_stage_qkv(smb, Bh, Bl, mbase, nbase, (ck + 2) * BK, (ck + 2) % 3, tid);
            CP_COMMIT();
        }

        const uint32_t sAhi = smb + buf * QSTAGE;
        const uint32_t sAlo = sAhi + QA_BYTES;
        const uint32_t sBhi = sAhi + 2 * QA_BYTES;
        const uint32_t sBlo = sBhi + QB_BYTES;

#pragma unroll
        for (int ks = 0; ks < 2; ++ks) {
            const int k0 = ks * 16;
            uint32_t ahi[4][4], alo[4][4];
#pragma unroll
            for (int mi = 0; mi < 4; ++mi) {
                uint32_t off = ((wm + mi * 16 + a_row) * SA + k0 + a_koff) * 2;
                ldmatrix_x4(ahi[mi], sAhi + off);
                ldmatrix_x4(alo[mi], sAlo + off);
            }
            uint32_t bhi[2][4], blo[2][4];
#pragma unroll
            for (int bi = 0; bi < 2; ++bi) {
                uint32_t off = ((wn + bi * 16 + b_row) * SA + k0 + b_koff) * 2;
                ldmatrix_x4(bhi[bi], sBhi + off);
                ldmatrix_x4(blo[bi], sBlo + off);
            }
#pragma unroll
            for (int mi = 0; mi < 4; ++mi)
#pragma unroll
                for (int ni = 0; ni < 4; ++ni) {
                    const int g = ni >> 1, h = (ni & 1) * 2;
                    mma_16816(acc[mi][ni], ahi[mi], bhi[g][h], bhi[g][h + 1]);
                }
#pragma unroll
            for (int mi = 0; mi < 4; ++mi)
#pragma unroll
                for (int ni = 0; ni < 4; ++ni) {
                    const int g = ni >> 1, h = (ni & 1) * 2;
                    mma_16816(acc[mi][ni], ahi[mi], blo[g][h], blo[g][h + 1]);
                }
#pragma unroll
            for (int mi = 0; mi < 4; ++mi)
#pragma unroll
                for (int ni = 0; ni < 4; ++ni) {
                    const int g = ni >> 1, h = (ni & 1) * 2;
                    mma_16816(acc[mi][ni], alo[mi], bhi[g][h], bhi[g][h + 1]);
                }
        }
    }

    const int fr = lane >> 2;
    const int fc = (lane & 3) * 2;
    const float qscale = (mode == 0) ? QSCALE : 1.0f;
#pragma unroll
    for (int mi = 0; mi < 4; ++mi) {
#pragma unroll
        for (int ni = 0; ni < 4; ++ni) {
            const int col = nbase + wn + ni * 8 + fc;
            const float b0 = bias[col], b1 = bias[col + 1];
            const int row0 = mbase + wm + mi * 16 + fr;
            const float v0 = (acc[mi][ni][0] + b0) * qscale;
            const float v1 = (acc[mi][ni][1] + b1) * qscale;
            const float v2 = (acc[mi][ni][2] + b0) * qscale;
            const float v3 = (acc[mi][ni][3] + b1) * qscale;
            // per-head layout: row0 = b*1024 + s ; col = h*64 + d
            const int bb = row0 >> 10, ss = row0 & 1023;
            const int hh = col >> 6,  dd = col & 63;
            const size_t dst = (((size_t)bb * HEADS + hh) * SEQ + ss) * HDIM + dd;
            if (mode == 2) {
                uint32_t h01, l01, h23, l23;
                split2h(v0, v1, h01, l01);
                split2h(v2, v3, h23, l23);
                *(uint32_t*)(g_Vhi + dst)            = h01;
                *(uint32_t*)(g_Vlo + dst)            = l01;
                *(uint32_t*)(g_Vhi + dst + 8 * HDIM) = h23;
                *(uint32_t*)(g_Vlo + dst + 8 * HDIM) = l23;
            } else {
                __nv_bfloat16* Chi = (mode == 0) ? g_Qhi : g_Khi;
                __nv_bfloat16* Clo = (mode == 0) ? g_Qlo : g_Klo;
                uint32_t h01, l01, h23, l23;
                split2(v0, v1, h01, l01);
                split2(v2, v3, h23, l23);
                *(uint32_t*)(Chi + dst)            = h01;
                *(uint32_t*)(Clo + dst)            = l01;
                *(uint32_t*)(Chi + dst + 8 * HDIM) = h23;
                *(uint32_t*)(Clo + dst + 8 * HDIM) = l23;
            }
        }
    }
}

// ==== out projection: fp16 2-term, 256x128 tile, 512 thr, 3-stage =========
#define OA_BYTES    (256 * SA * 2)          // 20480 (Z single fp16)
#define OB_BYTES    (128 * SA * 2)          // 10240 per Wo split
#define OSTAGE      (OA_BYTES + 2 * OB_BYTES)   // 40960
#define OGEMM_SMEM  (3 * OSTAGE)            // 122880

__device__ __forceinline__ void load_stage_out(
    uint32_t smb, int mbase, int nbase, int k0, int stage, int tid)
{
    const uint32_t sbase = smb + stage * OSTAGE;
#pragma unroll
    for (int i = 0; i < 2; ++i) {
        int idx = tid + i * 512;
        int r = idx >> 2, seg = idx & 3;
        uint32_t so = (r * SA + seg * 8) * 2;
        cp_async16(sbase + so, g_Z + (size_t)(mbase + r) * EMB + k0 + seg * 8);
    }
    {
        int r = tid >> 2, seg = tid & 3;
        uint32_t so = (r * SA + seg * 8) * 2;
        const size_t g = (size_t)(nbase + r) * EMB + k0 + seg * 8;
        cp_async16(sbase + OA_BYTES + so,            g_WOhi + g);
        cp_async16(sbase + OA_BYTES + OB_BYTES + so, g_WOlo + g);
    }
}

__global__ __launch_bounds__(512, 1)
void out_mma_kernel(const float* __restrict__ bo, float* __restrict__ out)
{
    extern __shared__ char sm[];
    const uint32_t smb = smem_u32(sm);
    const int tid  = threadIdx.x;          // 512 threads
    const int wid  = tid >> 5;
    const int lane = tid & 31;
    const int mbase = blockIdx.y * 256;
    const int nbase = blockIdx.x * 128;

    const int wm = (wid & 3) * 64;
    const int wn = (wid >> 2) * 32;

    float acc[4][4][4];
#pragma unroll
    for (int mi = 0; mi < 4; ++mi)
#pragma unroll
        for (int ni = 0; ni < 4; ++ni)
#pragma unroll
            for (int e = 0; e < 4; ++e) acc[mi][ni][e] = 0.f;

    const int a_row = (lane & 15);
    const int a_koff = (lane >> 4) * 8;
    const int b_row = (lane & 7) + ((lane >> 4) * 8);
    const int b_koff = ((lane >> 3) & 1) * 8;

    load_stage_out(smb, mbase, nbase, 0, 0, tid);
    CP_COMMIT();
    load_stage_out(smb, mbase, nbase, BK, 1, tid);
    CP_COMMIT();

    for (int ck = 0; ck < NCHUNK; ++ck) {
        const int buf = ck % 3;
        if (ck + 1 < NCHUNK) cp_wait<1>();
        else                 cp_wait<0>();
        __syncthreads();
        if (ck + 2 < NCHUNK) {
            load_stage_out(smb, mbase, nbase, (ck + 2) * BK, (ck + 2) % 3, tid);
            CP_COMMIT();
        }

        const uint32_t sA   = smb + buf * OSTAGE;
        const uint32_t sBhi = sA + OA_BYTES;
        const uint32_t sBlo = sBhi + OB_BYTES;

#pragma unroll
        for (int ks = 0; ks < 2; ++ks) {
            const int k0 = ks * 16;
            uint32_t a[4][4];
#pragma unroll
            for (int mi = 0; mi < 4; ++mi) {
                uint32_t off = ((wm + mi * 16 + a_row) * SA + k0 + a_koff) * 2;
                ldmatrix_x4(a[mi], sA + off);
            }
            uint32_t bhi[2][4], blo[2][4];
#pragma unroll
            for (int bi = 0; bi < 2; ++bi) {
                uint32_t off = ((wn + bi * 16 + b_row) * SA + k0 + b_koff) * 2;
                ldmatrix_x4(bhi[bi], sBhi + off);
                ldmatrix_x4(blo[bi], sBlo + off);
            }
#pragma unroll
            for (int mi = 0; mi < 4; ++mi)
#pragma unroll
                for (int ni = 0; ni < 4; ++ni) {
                    const int g = ni >> 1, h = (ni & 1) * 2;
                    mma_16816_f16(acc[mi][ni], a[mi], bhi[g][h], bhi[g][h + 1]);
                }
#pragma unroll
            for (int mi = 0; mi < 4; ++mi)
#pragma unroll
                for (int ni = 0; ni < 4; ++ni) {
                    const int g = ni >> 1, h = (ni & 1) * 2;
                    mma_16816_f16(acc[mi][ni], a[mi], blo[g][h], blo[g][h + 1]);
                }
        }
    }

    const int fr = lane >> 2;
    const int fc = (lane & 3) * 2;
#pragma unroll
    for (int mi = 0; mi < 4; ++mi) {
#pragma unroll
        for (int ni = 0; ni < 4; ++ni) {
            const int col = nbase + wn + ni * 8 + fc;
            const float b0 = bo[col], b1 = bo[col + 1];
            const int row0 = mbase + wm + mi * 16 + fr;
            float* p0 = out + (size_t)row0 * EMB + col;
            float* p1 = out + (size_t)(row0 + 8) * EMB + col;
            p0[0] = acc[mi][ni][0] + b0;
            p0[1] = acc[mi][ni][1] + b1;
            p1[0] = acc[mi][ni][2] + b0;
            p1[1] = acc[mi][ni][3] + b1;
        }
    }
}

// ================= Flash attention via HMMA (R12, unchanged) ===============
#define ASTR 72
#define Q_BYTES    (128 * ASTR * 2)          // 18432 per split
#define KVBUF      (4 * 64 * ASTR * 2)       // 36864: Kh,Kl,Vh,Vl
#define ATTN_SMEM  (2 * Q_BYTES + 2 * KVBUF) // 110592
#define ATTN_G     18
#define BARCNT     320
#define NBAR_E0    1
#define NBAR_E1    2
#define NBAR_F0    3
#define NBAR_F1    4

__device__ __forceinline__ void attn_load_kv64(uint32_t kvbase, size_t gbase,
                                               int jb, int tid64)
{
#pragma unroll
    for (int i = 0; i < 8; ++i) {
        int idx = tid64 + i * 64;                // 0..511
        int r = idx >> 3, seg = idx & 7;
        const size_t g = gbase + (size_t)(jb * 64 + r) * HDIM + seg * 8;
        const uint32_t so = (r * ASTR + seg * 8) * 2;
        cp_async16(kvbase + so,                  g_Khi + g);
        cp_async16(kvbase + 64 * ASTR * 2 + so,  g_Klo + g);
        cp_async16(kvbase + 128 * ASTR * 2 + so, g_Vhi + g);
        cp_async16(kvbase + 192 * ASTR * 2 + so, g_Vlo + g);
    }
}

__device__ __forceinline__ void attn_load_q(uint32_t uQh, uint32_t uQl,
                                            size_t gbase, int qb, int tid)
{
#pragma unroll
    for (int i = 0; i < 4; ++i) {
        int idx = tid + i * 256;
        int r = idx >> 3, seg = idx & 7;
        const size_t g = gbase + (size_t)(qb * 128 + r) * HDIM + seg * 8;
        const uint32_t so = (r * ASTR + seg * 8) * 2;
        cp_async16(uQh + so, g_Qhi + g);
        cp_async16(uQl + so, g_Qlo + g);
    }
}

__global__ __launch_bounds__(256, 2) void attn_mma_kernel()
{
    extern __shared__ char smraw[];
    const uint32_t uQh  = smem_u32(smraw);
    const uint32_t uQl  = uQh + Q_BYTES;
    const uint32_t uKV0 = uQl + Q_BYTES;

    const int tid = threadIdx.x, wid = tid >> 5, lane = tid & 31;
    const int pp = blockIdx.x;               // 0..3 (pair index)
    const int bh = blockIdx.y;               // 0..63
    const size_t gbase = (size_t)bh * SEQ * HDIM;
    const int qa = 7 - pp;
    const int cb = 2 * qa + 2;               // tiles consumed by first q-tile

    attn_load_q(uQh, uQl, gbase, qa, tid);
    CP_COMMIT();
    cp_wait<0>();
    __syncthreads();                         // Q visible

    if (wid < 2) {
        attn_load_kv64(uKV0, gbase, 0, tid);
        CP_COMMIT();
        attn_load_kv64(uKV0 + KVBUF, gbase, 1, tid);
        CP_COMMIT();
        cp_wait<1>();                        // tile 0 complete
        BAR_ARRIVE(NBAR_F0, BARCNT);
    }

    float o[8][4];
#pragma unroll
    for (int nt = 0; nt < 8; ++nt)
#pragma unroll
        for (int e = 0; e < 4; ++e) o[nt][e] = 0.f;
    float m0 = -1e30f, m1 = -1e30f, l0 = 0.f, l1 = 0.f;

    int qb = qa;
    int r0g = qb * 128 + wid * 16 + (lane >> 2);

    const int a_row = lane & 15;
    const int a_koff = (lane >> 4) * 8;
    const int b_row = (lane & 7) + ((lane >> 4) * 8);
    const int b_koff = ((lane >> 3) & 1) * 8;

    for (int c = 0; c < ATTN_G; ++c) {
        if (c == cb) {
            const float i0 = 1.f / l0, i1 = 1.f / l1;
            const int r0 = wid * 16 + (lane >> 2);
            const size_t zr0 = ((size_t)bh * SEQ + (size_t)qb * 128 + r0) * HDIM;
#pragma unroll
            for (int nt = 0; nt < 8; ++nt) {
                const int cc = nt * 8 + (lane & 3) * 2;
                *(uint32_t*)(g_Z + zr0 + cc) = packh2(o[nt][0] * i0, o[nt][1] * i0);
                *(uint32_t*)(g_Z + zr0 + 8 * HDIM + cc) = packh2(o[nt][2] * i1, o[nt][3] * i1);
            }
#pragma unroll
            for (int nt = 0; nt < 8; ++nt)
#pragma unroll
                for (int e = 0; e < 4; ++e) o[nt][e] = 0.f;
            m0 = -1e30f; m1 = -1e30f; l0 = 0.f; l1 = 0.f;
            qb = pp;
            r0g = qb * 128 + wid * 16 + (lane >> 2);
            __syncthreads();
            attn_load_q(uQh, uQl, gbase, qb, tid);
            CP_COMMIT();
            cp_wait<0>();
            __syncthreads();
        }

        BAR_SYNC_N((c & 1) ? NBAR_F1 : NBAR_F0, BARCNT);
        const uint32_t kvb = uKV0 + (c & 1) * KVBUF;
        const uint32_t uKh = kvb;
        const uint32_t uKl = kvb + 64 * ASTR * 2;
        const uint32_t uVh = kvb + 128 * ASTR * 2;
        const uint32_t uVl = kvb + 192 * ASTR * 2;
        const int jb = (c < cb) ? c : c - cb;

        float s[8][4];
#pragma unroll
        for (int nt = 0; nt < 8; ++nt)
#pragma unroll
            for (int e = 0; e < 4; ++e) s[nt][e] = 0.f;

#pragma unroll
        for (int ks = 0; ks < 4; ++ks) {
            uint32_t qh[4], ql[4];
            {
                uint32_t off = ((wid * 16 + a_row) * ASTR + ks * 16 + a_koff) * 2;
                ldmatrix_x4(qh, uQh + off);
                ldmatrix_x4(ql, uQl + off);
            }
            uint32_t kh[4][4], kl[4][4];
#pragma unroll
            for (int g = 0; g < 4; ++g) {
                uint32_t off = ((g * 16 + b_row) * ASTR + ks * 16 + b_koff) * 2;
                ldmatrix_x4(kh[g], uKh + off);
                ldmatrix_x4(kl[g], uKl + off);
            }
#pragma unroll
            for (int g = 0; g < 4; ++g)
#pragma unroll
                for (int hh = 0; hh < 2; ++hh)
                    mma_16816(s[2 * g + hh], qh, kh[g][hh * 2], kh[g][hh * 2 + 1]);
#pragma unroll
            for (int g = 0; g < 4; ++g)
#pragma unroll
                for (int hh = 0; hh < 2; ++hh)
                    mma_16816(s[2 * g + hh], qh, kl[g][hh * 2], kl[g][hh * 2 + 1]);
#pragma unroll
            for (int g = 0; g < 4; ++g)
#pragma unroll
                for (int hh = 0; hh < 2; ++hh)
                    mma_16816(s[2 * g + hh], ql, kh[g][hh * 2], kh[g][hh * 2 + 1]);
        }

        const bool needmask = (jb >= 2 * qb);
        float mx0 = -1e30f, mx1 = -1e30f;
#pragma unroll
        for (int nt = 0; nt < 8; ++nt) {
            if (needmask) {
                const int cc = jb * 64 + nt * 8 + (lane & 3) * 2;
                s[nt][0] = (cc     <= r0g)     ? s[nt][0] : -1e30f;
                s[nt][1] = (cc + 1 <= r0g)     ? s[nt][1] : -1e30f;
                s[nt][2] = (cc     <= r0g + 8) ? s[nt][2] : -1e30f;
                s[nt][3] = (cc + 1 <= r0g + 8) ? s[nt][3] : -1e30f;
            }
            mx0 = fmaxf(mx0, fmaxf(s[nt][0], s[nt][1]));
            mx1 = fmaxf(mx1, fmaxf(s[nt][2], s[nt][3]));
        }
        mx0 = fmaxf(mx0, __shfl_xor_sync(0xffffffffu, mx0, 1));
        mx0 = fmaxf(mx0, __shfl_xor_sync(0xffffffffu, mx0, 2));
        mx1 = fmaxf(mx1, __shfl_xor_sync(0xffffffffu, mx1, 1));
        mx1 = fmaxf(mx1, __shfl_xor_sync(0xffffffffu, mx1, 2));

        const float nm0 = fmaxf(m0, mx0), nm1 = fmaxf(m1, mx1);
        const float al0 = exp2f(m0 - nm0), al1 = exp2f(m1 - nm1);
        m0 = nm0; m1 = nm1;

#pragma unroll
        for (int nt = 0; nt < 8; ++nt) {
            o[nt][0] *= al0; o[nt][1] *= al0;
            o[nt][2] *= al1; o[nt][3] *= al1;
        }

        float rs0 = 0.f, rs1 = 0.f;
#pragma unroll
        for (int ks = 0; ks < 4; ++ks) {
            float* sa = s[2 * ks];
            float* sb = s[2 * ks + 1];
            sa[0] = exp2f(sa[0] - m0);
            sa[1] = exp2f(sa[1] - m0);
            sa[2] = exp2f(sa[2] - m1);
            sa[3] = exp2f(sa[3] - m1);
            sb[0] = exp2f(sb[0] - m0);
            sb[1] = exp2f(sb[1] - m0);
            sb[2] = exp2f(sb[2] - m1);
            sb[3] = exp2f(sb[3] - m1);
            rs0 += sa[0] + sa[1] + sb[0] + sb[1];
            rs1 += sa[2] + sa[3] + sb[2] + sb[3];

            uint32_t ph[4];
            ph[0] = packh2(sa[0], sa[1]);
            ph[1] = packh2(sa[2], sa[3]);
            ph[2] = packh2(sb[0], sb[1]);
            ph[3] = packh2(sb[2], sb[3]);

            uint32_t vh[4][4], vl[4][4];
#pragma unroll
            for (int dg = 0; dg < 4; ++dg) {
                uint32_t off = (((lane & 15) + ks * 16) * ASTR + dg * 16 + (lane >> 4) * 8) * 2;
                ldmatrix_x4_trans(vh[dg], uVh + off);
                ldmatrix_x4_trans(vl[dg], uVl + off);
            }
#pragma unroll
            for (int dg = 0; dg < 4; ++dg)
#pragma unroll
                for (int hh = 0; hh < 2; ++hh)
                    mma_16816_f16(o[2 * dg + hh], ph, vh[dg][hh * 2], vh[dg][hh * 2 + 1]);
#pragma unroll
            for (int dg = 0; dg < 4; ++dg)
#pragma unroll
                for (int hh = 0; hh < 2; ++hh)
                    mma_16816_f16(o[2 * dg + hh], ph, vl[dg][hh * 2], vl[dg][hh * 2 + 1]);
        }

        BAR_ARRIVE((c & 1) ? NBAR_E1 : NBAR_E0, BARCNT);

        if (wid < 2) {
            const bool refill = (c + 2 < ATTN_G);
            if (refill) {
                BAR_SYNC_N((c & 1) ? NBAR_E1 : NBAR_E0, BARCNT);
                const int g = c + 2;
                const int gj = (g < cb) ? g : g - cb;
                attn_load_kv64(uKV0 + (g & 1) * KVBUF, gbase, gj, tid);
                CP_COMMIT();
            }
            if (c + 1 < ATTN_G) {
                if (refill) cp_wait<1>();
                else        cp_wait<0>();
                BAR_ARRIVE(((c + 1) & 1) ? NBAR_F1 : NBAR_F0, BARCNT);
            }
        }

        rs0 += __shfl_xor_sync(0xffffffffu, rs0, 1);
        rs0 += __shfl_xor_sync(0xffffffffu, rs0, 2);
        rs1 += __shfl_xor_sync(0xffffffffu, rs1, 1);
        rs1 += __shfl_xor_sync(0xffffffffu, rs1, 2);
        l0 = l0 * al0 + rs0;
        l1 = l1 * al1 + rs1;
    }

    const float inv0 = 1.f / l0, inv1 = 1.f / l1;
    const int r0 = wid * 16 + (lane >> 2);
    const size_t zr0 = ((size_t)bh * SEQ + (size_t)qb * 128 + r0) * HDIM;
#pragma unroll
    for (int nt = 0; nt < 8; ++nt) {
        const int cc = nt * 8 + (lane & 3) * 2;
        *(uint32_t*)(g_Z + zr0 + cc) = packh2(o[nt][0] * inv0, o[nt][1] * inv0);
        *(uint32_t*)(g_Z + zr0 + 8 * HDIM + cc) = packh2(o[nt][2] * inv1, o[nt][3] * inv1);
    }
}

// ---------------- launch ----------------
extern "C" void kernel_launch(void* const* d_in, const int* in_sizes, int n_in,
                              void* d_out, int out_size)
{
    const float* X  = (const float*)d_in[0];
    const float* wq = (const float*)d_in[2];
    const float* bq = (const float*)d_in[3];
    const float* wk = (const float*)d_in[4];
    const float* bk = (const float*)d_in[5];
    const float* wv = (const float*)d_in[6];
    const float* bv = (const float*)d_in[7];
    const float* wo = (const float*)d_in[8];
    const float* bo = (const float*)d_in[9];
    float* out = (float*)d_out;

    __nv_bfloat16 *Xhi, *Xlo;
    cudaGetSymbolAddress((void**)&Xhi, g_Xhi);
    cudaGetSymbolAddress((void**)&Xlo, g_Xlo);

    cudaFuncSetAttribute(attn_mma_kernel, cudaFuncAttributeMaxDynamicSharedMemorySize, ATTN_SMEM);
    cudaFuncSetAttribute(qkv_mma_kernel, cudaFuncAttributeMaxDynamicSharedMemorySize, GEMM_SMEM);
    cudaFuncSetAttribute(out_mma_kernel, cudaFuncAttributeMaxDynamicSharedMemorySize, OGEMM_SMEM);

    // split X into bf16 hi/lo; split+transpose 4 weight matrices (wo -> fp16)
    cvt_split_kernel<<<(MROWS * EMB / 4) / 256, 256>>>(X, Xhi, Xlo);
    cvt_splitT_kernel<<<dim3(EMB / 32, EMB / 32, 4), 256>>>(wq, wk, wv, wo);

    // QKV projections: 256x128 tiles, 512 threads, 3-stage pipeline
    qkv_mma_kernel<<<dim3(EMB / 128, MROWS / 256, 3), 512, GEMM_SMEM>>>(bq, bk, bv);

    // causal flash attention, diagonal-paired, producer/consumer -> g_Z (fp16)
    attn_mma_kernel<<<dim3(4, BATCH * HEADS), 256, ATTN_SMEM>>>();

    // output projection: fp16 2-term, 256x128 tiles, 512 threads, 3-stage
    out_mma_kernel<<<dim3(EMB / 128, MROWS / 256), 512, OGEMM_SMEM>>>(bo, out);

    (void)in_sizes; (void)n_in; (void)out_size;
}

// round 15
// speedup vs baseline: 1.0739x; 1.0739x over previous
#include <cuda_runtime.h>
#include <cuda_bf16.h>
#include <cuda_fp16.h>
#include <cstdint>

// Problem constants
#define BATCH   4
#define SEQ     1024
#define EMB     1024
#define HEADS   16
#define HDIM    64
#define MROWS   (BATCH * SEQ)      // 4096

// ---------------- scratch (16B-aligned for cp.async) ----------------
__device__ __align__(256) __nv_bfloat16 g_Xhi[MROWS * EMB];
__device__ __align__(256) __nv_bfloat16 g_Xlo[MROWS * EMB];
__device__ __align__(256) __half       g_Xh [MROWS * EMB];   // X single fp16
// Q/K in per-head layout [B, H, S, HDIM], bf16 hi/lo; V fp16 hi/lo
__device__ __align__(256) __nv_bfloat16 g_Qhi[MROWS * EMB];
__device__ __align__(256) __nv_bfloat16 g_Qlo[MROWS * EMB];
__device__ __align__(256) __nv_bfloat16 g_Khi[MROWS * EMB];
__device__ __align__(256) __nv_bfloat16 g_Klo[MROWS * EMB];
__device__ __align__(256) __half       g_Vhi[MROWS * EMB];
__device__ __align__(256) __half       g_Vlo[MROWS * EMB];
// Z single fp16
__device__ __align__(256) __half       g_Z[MROWS * EMB];
// wq,wk transposed [N,K] bf16 hi/lo; wv & wo transposed [N,K] fp16 hi/lo
__device__ __align__(256) __nv_bfloat16 g_Whi[2 * EMB * EMB];
__device__ __align__(256) __nv_bfloat16 g_Wlo[2 * EMB * EMB];
__device__ __align__(256) __half       g_WVhi[EMB * EMB];
__device__ __align__(256) __half       g_WVlo[EMB * EMB];
__device__ __align__(256) __half       g_WOhi[EMB * EMB];
__device__ __align__(256) __half       g_WOlo[EMB * EMB];

// ================= PTX helpers (sm_80+ subset only) =============
__device__ __forceinline__ uint32_t smem_u32(const void* p) {
    uint32_t a;
    asm("{ .reg .u64 t; cvta.to.shared.u64 t, %1; cvt.u32.u64 %0, t; }" : "=r"(a) : "l"(p));
    return a;
}

__device__ __forceinline__ void cp_async16(uint32_t saddr, const void* gaddr) {
    asm volatile("cp.async.cg.shared.global [%0], [%1], 16;" :: "r"(saddr), "l"(gaddr));
}
#define CP_COMMIT()  asm volatile("cp.async.commit_group;" ::: "memory")
template <int N>
__device__ __forceinline__ void cp_wait() {
    asm volatile("cp.async.wait_group %0;" :: "n"(N) : "memory");
}

#define BAR_ARRIVE(id, cnt) \
    asm volatile("bar.arrive %0, %1;" :: "r"((int)(id)), "r"((int)(cnt)) : "memory")
#define BAR_SYNC_N(id, cnt) \
    asm volatile("bar.sync %0, %1;" :: "r"((int)(id)), "r"((int)(cnt)) : "memory")

__device__ __forceinline__ void ldmatrix_x4(uint32_t (&r)[4], uint32_t addr) {
    asm volatile("ldmatrix.sync.aligned.m8n8.x4.shared.b16 {%0,%1,%2,%3}, [%4];"
                 : "=r"(r[0]), "=r"(r[1]), "=r"(r[2]), "=r"(r[3]) : "r"(addr));
}
__device__ __forceinline__ void ldmatrix_x4_trans(uint32_t (&r)[4], uint32_t addr) {
    asm volatile("ldmatrix.sync.aligned.m8n8.x4.trans.shared.b16 {%0,%1,%2,%3}, [%4];"
                 : "=r"(r[0]), "=r"(r[1]), "=r"(r[2]), "=r"(r[3]) : "r"(addr));
}

__device__ __forceinline__ void mma_16816(float (&d)[4], const uint32_t (&a)[4],
                                          uint32_t b0, uint32_t b1) {
    asm volatile(
        "mma.sync.aligned.m16n8k16.row.col.f32.bf16.bf16.f32 "
        "{%0,%1,%2,%3}, {%4,%5,%6,%7}, {%8,%9}, {%0,%1,%2,%3};"
        : "+f"(d[0]), "+f"(d[1]), "+f"(d[2]), "+f"(d[3])
        : "r"(a[0]), "r"(a[1]), "r"(a[2]), "r"(a[3]), "r"(b0), "r"(b1));
}
__device__ __forceinline__ void mma_16816_f16(float (&d)[4], const uint32_t (&a)[4],
                                              uint32_t b0, uint32_t b1) {
    asm volatile(
        "mma.sync.aligned.m16n8k16.row.col.f32.f16.f16.f32 "
        "{%0,%1,%2,%3}, {%4,%5,%6,%7}, {%8,%9}, {%0,%1,%2,%3};"
        : "+f"(d[0]), "+f"(d[1]), "+f"(d[2]), "+f"(d[3])
        : "r"(a[0]), "r"(a[1]), "r"(a[2]), "r"(a[3]), "r"(b0), "r"(b1));
}

// fp32 pair -> packed bf16x2 hi + lo
__device__ __forceinline__ void split2(float x, float y, uint32_t& hi, uint32_t& lo) {
    __nv_bfloat16 hx = __float2bfloat16(x);
    __nv_bfloat16 hy = __float2bfloat16(y);
    __nv_bfloat16 lx = __float2bfloat16(x - __bfloat162float(hx));
    __nv_bfloat16 ly = __float2bfloat16(y - __bfloat162float(hy));
    __nv_bfloat162 hp(hx, hy), lp(lx, ly);
    hi = *(uint32_t*)&hp;
    lo = *(uint32_t*)&lp;
}
// fp32 pair -> packed fp16x2 hi + lo
__device__ __forceinline__ void split2h(float x, float y, uint32_t& hi, uint32_t& lo) {
    __half hx = __float2half_rn(x);
    __half hy = __float2half_rn(y);
    __half lx = __float2half_rn(x - __half2float(hx));
    __half ly = __float2half_rn(y - __half2float(hy));
    __half2 hp(hx, hy), lp(lx, ly);
    hi = *(uint32_t*)&hp;
    lo = *(uint32_t*)&lp;
}
__device__ __forceinline__ uint32_t packh2(float x, float y) {
    __half2 h = __floats2half2_rn(x, y);
    return *(uint32_t*)&h;
}

// ================= conversion kernels =================
__global__ __launch_bounds__(256) void cvt_split_kernel(
    const float* __restrict__ src, __nv_bfloat16* __restrict__ hi,
    __nv_bfloat16* __restrict__ lo, __half* __restrict__ h16)
{
    int i = blockIdx.x * blockDim.x + threadIdx.x;     // one float4 each
    float4 v = ((const float4*)src)[i];
    uint32_t h0, l0, h1, l1;
    split2(v.x, v.y, h0, l0);
    split2(v.z, v.w, h1, l1);
    ((uint2*)hi)[i] = make_uint2(h0, h1);
    ((uint2*)lo)[i] = make_uint2(l0, l1);
    ((uint2*)h16)[i] = make_uint2(packh2(v.x, v.y), packh2(v.z, v.w));
}

// W [K,N] fp32 -> WT [N,K] hi/lo. z<2: bf16 (wq,wk); z==2: fp16 wv; z==3: fp16 wo.
__global__ __launch_bounds__(256) void cvt_splitT_kernel(
    const float* __restrict__ w0, const float* __restrict__ w1,
    const float* __restrict__ w2, const float* __restrict__ w3)
{
    __shared__ float t[32][33];
    const int z = blockIdx.z;
    const float* W = (z == 0) ? w0 : (z == 1) ? w1 : (z == 2) ? w2 : w3;
    const int bx = blockIdx.x * 32;   // N base
    const int by = blockIdx.y * 32;   // K base
    const int tx = threadIdx.x & 31;
    const int ty = threadIdx.x >> 5;  // 0..7
    for (int i = ty; i < 32; i += 8)
        t[i][tx] = W[(size_t)(by + i) * EMB + bx + tx];
    __syncthreads();
    if (z < 2) {
        __nv_bfloat16* hiT = g_Whi + (size_t)z * EMB * EMB;
        __nv_bfloat16* loT = g_Wlo + (size_t)z * EMB * EMB;
        for (int i = ty; i < 32; i += 8) {
            float v = t[tx][i];
            __nv_bfloat16 h = __float2bfloat16(v);
            __nv_bfloat16 l = __float2bfloat16(v - __bfloat162float(h));
            hiT[(size_t)(bx + i) * EMB + by + tx] = h;
            loT[(size_t)(bx + i) * EMB + by + tx] = l;
        }
    } else {
        __half* hiT = (z == 2) ? g_WVhi : g_WOhi;
        __half* loT = (z == 2) ? g_WVlo : g_WOlo;
        for (int i = ty; i < 32; i += 8) {
            float v = t[tx][i];
            __half h = __float2half_rn(v);
            __half l = __float2half_rn(v - __half2float(h));
            hiT[(size_t)(bx + i) * EMB + by + tx] = h;
            loT[(size_t)(bx + i) * EMB + by + tx] = l;
        }
    }
}

// ================= HMMA bf16x3 Q/K GEMM (R12 shape) =================
#define BK          32
#define NCHUNK      (EMB / BK)              // 32
#define SA          40                       // smem row stride (elems)
#define SPLIT_BYTES (128 * SA * 2)          // 10240
#define STAGE_BYTES (4 * SPLIT_BYTES)       // 40960
#define GEMM_SMEM   (2 * STAGE_BYTES)       // 81920

// Q pre-scale: 1/16^0.25 * log2(e)  (softmax done in exp2 domain)
#define QSCALE (0.5f * 1.4426950408889634f)

__device__ __forceinline__ void load_stage_async(
    uint32_t smb, const __nv_bfloat16* __restrict__ Ahi, const __nv_bfloat16* __restrict__ Alo,
    const __nv_bfloat16* __restrict__ Bhi, const __nv_bfloat16* __restrict__ Blo,
    int mbase, int nbase, int k0, int buf, int tid)
{
    const __nv_bfloat16* gsrc[4] = {
        Ahi + (size_t)mbase * EMB + k0, Alo + (size_t)mbase * EMB + k0,
        Bhi + (size_t)nbase * EMB + k0, Blo + (size_t)nbase * EMB + k0 };
    const uint32_t sbase = smb + buf * STAGE_BYTES;
#pragma unroll
    for (int m = 0; m < 4; ++m) {
#pragma unroll
        for (int i = 0; i < 2; ++i) {
            int idx = tid + i * 256;
            int r = idx >> 2, seg = idx & 3;
            uint32_t sa = sbase + m * SPLIT_BYTES + (r * SA + seg * 8) * 2;
            cp_async16(sa, gsrc[m] + (size_t)r * EMB + seg * 8);
        }
    }
}

// mode 0: Q (bf16 split, xQSCALE); mode 1: K (bf16 split)
__global__ __launch_bounds__(256, 2)
void qk_mma_kernel(const float* __restrict__ bq, const float* __restrict__ bk)
{
    extern __shared__ char sm[];
    const uint32_t smb = smem_u32(sm);
    const int tid  = threadIdx.x;
    const int wid  = tid >> 5;
    const int lane = tid & 31;
    const int mbase = blockIdx.y * 128;
    const int nbase = blockIdx.x * 128;
    const int mode = blockIdx.z;

    const __nv_bfloat16* Bh = g_Whi + (size_t)mode * EMB * EMB;
    const __nv_bfloat16* Bl = g_Wlo + (size_t)mode * EMB * EMB;
    const float* bias = (mode == 0) ? bq : bk;

    const int wm = (wid & 1) * 64;
    const int wn = (wid >> 1) * 32;

    float acc[4][4][4];
#pragma unroll
    for (int mi = 0; mi < 4; ++mi)
#pragma unroll
        for (int ni = 0; ni < 4; ++ni)
#pragma unroll
            for (int e = 0; e < 4; ++e) acc[mi][ni][e] = 0.f;

    const int a_row = (lane & 15);
    const int a_koff = (lane >> 4) * 8;
    const int b_row = (lane & 7) + ((lane >> 4) * 8);
    const int b_koff = ((lane >> 3) & 1) * 8;

    load_stage_async(smb, g_Xhi, g_Xlo, Bh, Bl, mbase, nbase, 0, 0, tid);
    CP_COMMIT();

    for (int ck = 0; ck < NCHUNK; ++ck) {
        const int buf = ck & 1;
        cp_wait<0>();
        __syncthreads();
        if (ck + 1 < NCHUNK) {
            load_stage_async(smb, g_Xhi, g_Xlo, Bh, Bl, mbase, nbase, (ck + 1) * BK, buf ^ 1, tid);
            CP_COMMIT();
        }

        const uint32_t sAhi = smb + buf * STAGE_BYTES;
        const uint32_t sAlo = sAhi + SPLIT_BYTES;
        const uint32_t sBhi = sAhi + 2 * SPLIT_BYTES;
        const uint32_t sBlo = sAhi + 3 * SPLIT_BYTES;

#pragma unroll
        for (int ks = 0; ks < 2; ++ks) {
            const int k0 = ks * 16;
            uint32_t ahi[4][4], alo[4][4];
#pragma unroll
            for (int mi = 0; mi < 4; ++mi) {
                uint32_t off = ((wm + mi * 16 + a_row) * SA + k0 + a_koff) * 2;
                ldmatrix_x4(ahi[mi], sAhi + off);
                ldmatrix_x4(alo[mi], sAlo + off);
            }
            uint32_t bhi[2][4], blo[2][4];
#pragma unroll
            for (int bi = 0; bi < 2; ++bi) {
                uint32_t off = ((wn + bi * 16 + b_row) * SA + k0 + b_koff) * 2;
                ldmatrix_x4(bhi[bi], sBhi + off);
                ldmatrix_x4(blo[bi], sBlo + off);
            }
#pragma unroll
            for (int mi = 0; mi < 4; ++mi)
#pragma unroll
                for (int ni = 0; ni < 4; ++ni) {
                    const int g = ni >> 1, h = (ni & 1) * 2;
                    mma_16816(acc[mi][ni], ahi[mi], bhi[g][h], bhi[g][h + 1]);
                }
#pragma unroll
            for (int mi = 0; mi < 4; ++mi)
#pragma unroll
                for (int ni = 0; ni < 4; ++ni) {
                    const int g = ni >> 1, h = (ni & 1) * 2;
                    mma_16816(acc[mi][ni], ahi[mi], blo[g][h], blo[g][h + 1]);
                }
#pragma unroll
            for (int mi = 0; mi < 4; ++mi)
#pragma unroll
                for (int ni = 0; ni < 4; ++ni) {
                    const int g = ni >> 1, h = (ni & 1) * 2;
                    mma_16816(acc[mi][ni], alo[mi], bhi[g][h], bhi[g][h + 1]);
                }
        }
    }

    const int fr = lane >> 2;
    const int fc = (lane & 3) * 2;
    const float qscale = (mode == 0) ? QSCALE : 1.0f;
    __nv_bfloat16* Chi = (mode == 0) ? g_Qhi : g_Khi;
    __nv_bfloat16* Clo = (mode == 0) ? g_Qlo : g_Klo;
#pragma unroll
    for (int mi = 0; mi < 4; ++mi) {
#pragma unroll
        for (int ni = 0; ni < 4; ++ni) {
            const int col = nbase + wn + ni * 8 + fc;
            const float b0 = bias[col], b1 = bias[col + 1];
            const int row0 = mbase + wm + mi * 16 + fr;
            const float v0 = (acc[mi][ni][0] + b0) * qscale;
            const float v1 = (acc[mi][ni][1] + b1) * qscale;
            const float v2 = (acc[mi][ni][2] + b0) * qscale;
            const float v3 = (acc[mi][ni][3] + b1) * qscale;
            // per-head layout: row0 = b*1024 + s ; col = h*64 + d
            const int bb = row0 >> 10, ss = row0 & 1023;
            const int hh = col >> 6,  dd = col & 63;
            const size_t dst = (((size_t)bb * HEADS + hh) * SEQ + ss) * HDIM + dd;
            uint32_t h01, l01, h23, l23;
            split2(v0, v1, h01, l01);
            split2(v2, v3, h23, l23);
            *(uint32_t*)(Chi + dst)            = h01;
            *(uint32_t*)(Clo + dst)            = l01;
            *(uint32_t*)(Chi + dst + 8 * HDIM) = h23;
            *(uint32_t*)(Clo + dst + 8 * HDIM) = l23;
        }
    }
}

// ===== fp16 2-term GEMM body (A single fp16, B fp16 hi/lo) =====
#define OSTAGE_BYTES (3 * SPLIT_BYTES)       // 30720: A, Bhi, Blo
#define OGEMM_SMEM   (2 * OSTAGE_BYTES)      // 61440

__device__ __forceinline__ void load_stage_h3(
    uint32_t smb, const __half* __restrict__ A,
    const __half* __restrict__ Bh, const __half* __restrict__ Bl,
    int mbase, int nbase, int k0, int buf, int tid)
{
    const __half* gsrc[3] = {
        A  + (size_t)mbase * EMB + k0,
        Bh + (size_t)nbase * EMB + k0,
        Bl + (size_t)nbase * EMB + k0 };
    const uint32_t sbase = smb + buf * OSTAGE_BYTES;
#pragma unroll
    for (int m = 0; m < 3; ++m) {
#pragma unroll
        for (int i = 0; i < 2; ++i) {
            int idx = tid + i * 256;
            int r = idx >> 2, seg = idx & 3;
            uint32_t sa = sbase + m * SPLIT_BYTES + (r * SA + seg * 8) * 2;
            cp_async16(sa, gsrc[m] + (size_t)r * EMB + seg * 8);
        }
    }
}

// VOUT=true: epilogue writes V per-head fp16 hi/lo. VOUT=false: f32 to out.
template <bool VOUT>
__device__ __forceinline__ void gemm_body_h2(
    const __half* __restrict__ A, const __half* __restrict__ Bh,
    const __half* __restrict__ Bl, const float* __restrict__ bias,
    float* __restrict__ outf)
{
    extern __shared__ char sm[];
    const uint32_t smb = smem_u32(sm);
    const int tid  = threadIdx.x;
    const int wid  = tid >> 5;
    const int lane = tid & 31;
    const int mbase = blockIdx.y * 128;
    const int nbase = blockIdx.x * 128;

    const int wm = (wid & 1) * 64;
    const int wn = (wid >> 1) * 32;

    float acc[4][4][4];
#pragma unroll
    for (int mi = 0; mi < 4; ++mi)
#pragma unroll
        for (int ni = 0; ni < 4; ++ni)
#pragma unroll
            for (int e = 0; e < 4; ++e) acc[mi][ni][e] = 0.f;

    const int a_row = (lane & 15);
    const int a_koff = (lane >> 4) * 8;
    const int b_row = (lane & 7) + ((lane >> 4) * 8);
    const int b_koff = ((lane >> 3) & 1) * 8;

    load_stage_h3(smb, A, Bh, Bl, mbase, nbase, 0, 0, tid);
    CP_COMMIT();

    for (int ck = 0; ck < NCHUNK; ++ck) {
        const int buf = ck & 1;
        cp_wait<0>();
        __syncthreads();
        if (ck + 1 < NCHUNK) {
            load_stage_h3(smb, A, Bh, Bl, mbase, nbase, (ck + 1) * BK, buf ^ 1, tid);
            CP_COMMIT();
        }

        const uint32_t sA   = smb + buf * OSTAGE_BYTES;
        const uint32_t sBhi = sA + SPLIT_BYTES;
        const uint32_t sBlo = sA + 2 * SPLIT_BYTES;

#pragma unroll
        for (int ks = 0; ks < 2; ++ks) {
            const int k0 = ks * 16;
            uint32_t a[4][4];
#pragma unroll
            for (int mi = 0; mi < 4; ++mi) {
                uint32_t off = ((wm + mi * 16 + a_row) * SA + k0 + a_koff) * 2;
                ldmatrix_x4(a[mi], sA + off);
            }
            uint32_t bhi[2][4], blo[2][4];
#pragma unroll
            for (int bi = 0; bi < 2; ++bi) {
                uint32_t off = ((wn + bi * 16 + b_row) * SA + k0 + b_koff) * 2;
                ldmatrix_x4(bhi[bi], sBhi + off);
                ldmatrix_x4(blo[bi], sBlo + off);
            }
#pragma unroll
            for (int mi = 0; mi < 4; ++mi)
#pragma unroll
                for (int ni = 0; ni < 4; ++ni) {
                    const int g = ni >> 1, h = (ni & 1) * 2;
                    mma_16816_f16(acc[mi][ni], a[mi], bhi[g][h], bhi[g][h + 1]);
                }
#pragma unroll
            for (int mi = 0; mi < 4; ++mi)
#pragma unroll
                for (int ni = 0; ni < 4; ++ni) {
                    const int g = ni >> 1, h = (ni & 1) * 2;
                    mma_16816_f16(acc[mi][ni], a[mi], blo[g][h], blo[g][h + 1]);
                }
        }
    }

    const int fr = lane >> 2;
    const int fc = (lane & 3) * 2;
#pragma unroll
    for (int mi = 0; mi < 4; ++mi) {
#pragma unroll
        for (int ni = 0; ni < 4; ++ni) {
            const int col = nbase + wn + ni * 8 + fc;
            const float b0 = bias[col], b1 = bias[col + 1];
            const int row0 = mbase + wm + mi * 16 + fr;
            const float v0 = acc[mi][ni][0] + b0;
            const float v1 = acc[mi][ni][1] + b1;
            const float v2 = acc[mi][ni][2] + b0;
            const float v3 = acc[mi][ni][3] + b1;
            if (VOUT) {
                // per-head layout V fp16 hi/lo
                const int bb = row0 >> 10, ss = row0 & 1023;
                const int hh = col >> 6,  dd = col & 63;
                const size_t dst = (((size_t)bb * HEADS + hh) * SEQ + ss) * HDIM + dd;
                uint32_t h01, l01, h23, l23;
                split2h(v0, v1, h01, l01);
                split2h(v2, v3, h23, l23);
                *(uint32_t*)(g_Vhi + dst)            = h01;
                *(uint32_t*)(g_Vlo + dst)            = l01;
                *(uint32_t*)(g_Vhi + dst + 8 * HDIM) = h23;
                *(uint32_t*)(g_Vlo + dst + 8 * HDIM) = l23;
            } else {
                float* p0 = outf + (size_t)row0 * EMB + col;
                float* p1 = outf + (size_t)(row0 + 8) * EMB + col;
                p0[0] = v0; p0[1] = v1;
                p1[0] = v2; p1[1] = v3;
            }
        }
    }
}

__global__ __launch_bounds__(256, 2)
void v_mma_kernel(const float* __restrict__ bv)
{
    gemm_body_h2<true>(g_Xh, g_WVhi, g_WVlo, bv, nullptr);
}

__global__ __launch_bounds__(256, 2)
void out_mma_kernel(const float* __restrict__ bo, float* __restrict__ out)
{
    gemm_body_h2<false>(g_Z, g_WOhi, g_WOlo, bo, out);
}

// ================= Flash attention via HMMA (R12, unchanged) ===============
#define ASTR 72
#define Q_BYTES    (128 * ASTR * 2)          // 18432 per split
#define KVBUF      (4 * 64 * ASTR * 2)       // 36864: Kh,Kl,Vh,Vl
#define ATTN_SMEM  (2 * Q_BYTES + 2 * KVBUF) // 110592
#define ATTN_G     18
#define BARCNT     320
#define NBAR_E0    1
#define NBAR_E1    2
#define NBAR_F0    3
#define NBAR_F1    4

__device__ __forceinline__ void attn_load_kv64(uint32_t kvbase, size_t gbase,
                                               int jb, int tid64)
{
#pragma unroll
    for (int i = 0; i < 8; ++i) {
        int idx = tid64 + i * 64;                // 0..511
        int r = idx >> 3, seg = idx & 7;
        const size_t g = gbase + (size_t)(jb * 64 + r) * HDIM + seg * 8;
        const uint32_t so = (r * ASTR + seg * 8) * 2;
        cp_async16(kvbase + so,                  g_Khi + g);
        cp_async16(kvbase + 64 * ASTR * 2 + so,  g_Klo + g);
        cp_async16(kvbase + 128 * ASTR * 2 + so, g_Vhi + g);
        cp_async16(kvbase + 192 * ASTR * 2 + so, g_Vlo + g);
    }
}

__device__ __forceinline__ void attn_load_q(uint32_t uQh, uint32_t uQl,
                                            size_t gbase, int qb, int tid)
{
#pragma unroll
    for (int i = 0; i < 4; ++i) {
        int idx = tid + i * 256;
        int r = idx >> 3, seg = idx & 7;
        const size_t g = gbase + (size_t)(qb * 128 + r) * HDIM + seg * 8;
        const uint32_t so = (r * ASTR + seg * 8) * 2;
        cp_async16(uQh + so, g_Qhi + g);
        cp_async16(uQl + so, g_Qlo + g);
    }
}

__global__ __launch_bounds__(256, 2) void attn_mma_kernel()
{
    extern __shared__ char smraw[];
    const uint32_t uQh  = smem_u32(smraw);
    const uint32_t uQl  = uQh + Q_BYTES;
    const uint32_t uKV0 = uQl + Q_BYTES;

    const int tid = threadIdx.x, wid = tid >> 5, lane = tid & 31;
    const int pp = blockIdx.x;               // 0..3 (pair index)
    const int bh = blockIdx.y;               // 0..63
    const size_t gbase = (size_t)bh * SEQ * HDIM;
    const int qa = 7 - pp;
    const int cb = 2 * qa + 2;               // tiles consumed by first q-tile

    attn_load_q(uQh, uQl, gbase, qa, tid);
    CP_COMMIT();
    cp_wait<0>();
    __syncthreads();                         // Q visible

    if (wid < 2) {
        attn_load_kv64(uKV0, gbase, 0, tid);
        CP_COMMIT();
        attn_load_kv64(uKV0 + KVBUF, gbase, 1, tid);
        CP_COMMIT();
        cp_wait<1>();                        // tile 0 complete
        BAR_ARRIVE(NBAR_F0, BARCNT);
    }

    float o[8][4];
#pragma unroll
    for (int nt = 0; nt < 8; ++nt)
#pragma unroll
        for (int e = 0; e < 4; ++e) o[nt][e] = 0.f;
    float m0 = -1e30f, m1 = -1e30f, l0 = 0.f, l1 = 0.f;

    int qb = qa;
    int r0g = qb * 128 + wid * 16 + (lane >> 2);

    const int a_row = lane & 15;
    const int a_koff = (lane >> 4) * 8;
    const int b_row = (lane & 7) + ((lane >> 4) * 8);
    const int b_koff = ((lane >> 3) & 1) * 8;

    for (int c = 0; c < ATTN_G; ++c) {
        if (c == cb) {
            const float i0 = 1.f / l0, i1 = 1.f / l1;
            const int r0 = wid * 16 + (lane >> 2);
            const size_t zr0 = ((size_t)bh * SEQ + (size_t)qb * 128 + r0) * HDIM;
#pragma unroll
            for (int nt = 0; nt < 8; ++nt) {
                const int cc = nt * 8 + (lane & 3) * 2;
                *(uint32_t*)(g_Z + zr0 + cc) = packh2(o[nt][0] * i0, o[nt][1] * i0);
                *(uint32_t*)(g_Z + zr0 + 8 * HDIM + cc) = packh2(o[nt][2] * i1, o[nt][3] * i1);
            }
#pragma unroll
            for (int nt = 0; nt < 8; ++nt)
#pragma unroll
                for (int e = 0; e < 4; ++e) o[nt][e] = 0.f;
            m0 = -1e30f; m1 = -1e30f; l0 = 0.f; l1 = 0.f;
            qb = pp;
            r0g = qb * 128 + wid * 16 + (lane >> 2);
            __syncthreads();
            attn_load_q(uQh, uQl, gbase, qb, tid);
            CP_COMMIT();
            cp_wait<0>();
            __syncthreads();
        }

        BAR_SYNC_N((c & 1) ? NBAR_F1 : NBAR_F0, BARCNT);
        const uint32_t kvb = uKV0 + (c & 1) * KVBUF;
        const uint32_t uKh = kvb;
        const uint32_t uKl = kvb + 64 * ASTR * 2;
        const uint32_t uVh = kvb + 128 * ASTR * 2;
        const uint32_t uVl = kvb + 192 * ASTR * 2;
        const int jb = (c < cb) ? c : c - cb;

        float s[8][4];
#pragma unroll
        for (int nt = 0; nt < 8; ++nt)
#pragma unroll
            for (int e = 0; e < 4; ++e) s[nt][e] = 0.f;

#pragma unroll
        for (int ks = 0; ks < 4; ++ks) {
            uint32_t qh[4], ql[4];
            {
                uint32_t off = ((wid * 16 + a_row) * ASTR + ks * 16 + a_koff) * 2;
                ldmatrix_x4(qh, uQh + off);
                ldmatrix_x4(ql, uQl + off);
            }
            uint32_t kh[4][4], kl[4][4];
#pragma unroll
            for (int g = 0; g < 4; ++g) {
                uint32_t off = ((g * 16 + b_row) * ASTR + ks * 16 + b_koff) * 2;
                ldmatrix_x4(kh[g], uKh + off);
                ldmatrix_x4(kl[g], uKl + off);
            }
#pragma unroll
            for (int g = 0; g < 4; ++g)
#pragma unroll
                for (int hh = 0; hh < 2; ++hh)
                    mma_16816(s[2 * g + hh], qh, kh[g][hh * 2], kh[g][hh * 2 + 1]);
#pragma unroll
            for (int g = 0; g < 4; ++g)
#pragma unroll
                for (int hh = 0; hh < 2; ++hh)
                    mma_16816(s[2 * g + hh], qh, kl[g][hh * 2], kl[g][hh * 2 + 1]);
#pragma unroll
            for (int g = 0; g < 4; ++g)
#pragma unroll
                for (int hh = 0; hh < 2; ++hh)
                    mma_16816(s[2 * g + hh], ql, kh[g][hh * 2], kh[g][hh * 2 + 1]);
        }

        const bool needmask = (jb >= 2 * qb);
        float mx0 = -1e30f, mx1 = -1e30f;
#pragma unroll
        for (int nt = 0; nt < 8; ++nt) {
            if (needmask) {
                const int cc = jb * 64 + nt * 8 + (lane & 3) * 2;
                s[nt][0] = (cc     <= r0g)     ? s[nt][0] : -1e30f;
                s[nt][1] = (cc + 1 <= r0g)     ? s[nt][1] : -1e30f;
                s[nt][2] = (cc     <= r0g + 8) ? s[nt][2] : -1e30f;
                s[nt][3] = (cc + 1 <= r0g + 8) ? s[nt][3] : -1e30f;
            }
            mx0 = fmaxf(mx0, fmaxf(s[nt][0], s[nt][1]));
            mx1 = fmaxf(mx1, fmaxf(s[nt][2], s[nt][3]));
        }
        mx0 = fmaxf(mx0, __shfl_xor_sync(0xffffffffu, mx0, 1));
        mx0 = fmaxf(mx0, __shfl_xor_sync(0xffffffffu, mx0, 2));
        mx1 = fmaxf(mx1, __shfl_xor_sync(0xffffffffu, mx1, 1));
        mx1 = fmaxf(mx1, __shfl_xor_sync(0xffffffffu, mx1, 2));

        const float nm0 = fmaxf(m0, mx0), nm1 = fmaxf(m1, mx1);
        const float al0 = exp2f(m0 - nm0), al1 = exp2f(m1 - nm1);
        m0 = nm0; m1 = nm1;

#pragma unroll
        for (int nt = 0; nt < 8; ++nt) {
            o[nt][0] *= al0; o[nt][1] *= al0;
            o[nt][2] *= al1; o[nt][3] *= al1;
        }

        float rs0 = 0.f, rs1 = 0.f;
#pragma unroll
        for (int ks = 0; ks < 4; ++ks) {
            float* sa = s[2 * ks];
            float* sb = s[2 * ks + 1];
            sa[0] = exp2f(sa[0] - m0);
            sa[1] = exp2f(sa[1] - m0);
            sa[2] = exp2f(sa[2] - m1);
            sa[3] = exp2f(sa[3] - m1);
            sb[0] = exp2f(sb[0] - m0);
            sb[1] = exp2f(sb[1] - m0);
            sb[2] = exp2f(sb[2] - m1);
            sb[3] = exp2f(sb[3] - m1);
            rs0 += sa[0] + sa[1] + sb[0] + sb[1];
            rs1 += sa[2] + sa[3] + sb[2] + sb[3];

            uint32_t ph[4];
            ph[0] = packh2(sa[0], sa[1]);
            ph[1] = packh2(sa[2], sa[3]);
            ph[2] = packh2(sb[0], sb[1]);
            ph[3] = packh2(sb[2], sb[3]);

            uint32_t vh[4][4], vl[4][4];
#pragma unroll
            for (int dg = 0; dg < 4; ++dg) {
                uint32_t off = (((lane & 15) + ks * 16) * ASTR + dg * 16 + (lane >> 4) * 8) * 2;
                ldmatrix_x4_trans(vh[dg], uVh + off);
                ldmatrix_x4_trans(vl[dg], uVl + off);
            }
#pragma unroll
            for (int dg = 0; dg < 4; ++dg)
#pragma unroll
                for (int hh = 0; hh < 2; ++hh)
                    mma_16816_f16(o[2 * dg + hh], ph, vh[dg][hh * 2], vh[dg][hh * 2 + 1]);
#pragma unroll
            for (int dg = 0; dg < 4; ++dg)
#pragma unroll
                for (int hh = 0; hh < 2; ++hh)
                    mma_16816_f16(o[2 * dg + hh], ph, vl[dg][hh * 2], vl[dg][hh * 2 + 1]);
        }

        BAR_ARRIVE((c & 1) ? NBAR_E1 : NBAR_E0, BARCNT);

        if (wid < 2) {
            const bool refill = (c + 2 < ATTN_G);
            if (refill) {
                BAR_SYNC_N((c & 1) ? NBAR_E1 : NBAR_E0, BARCNT);
                const int g = c + 2;
                const int gj = (g < cb) ? g : g - cb;
                attn_load_kv64(uKV0 + (g & 1) * KVBUF, gbase, gj, tid);
                CP_COMMIT();
            }
            if (c + 1 < ATTN_G) {
                if (refill) cp_wait<1>();
                else        cp_wait<0>();
                BAR_ARRIVE(((c + 1) & 1) ? NBAR_F1 : NBAR_F0, BARCNT);
            }
        }

        rs0 += __shfl_xor_sync(0xffffffffu, rs0, 1);
        rs0 += __shfl_xor_sync(0xffffffffu, rs0, 2);
        rs1 += __shfl_xor_sync(0xffffffffu, rs1, 1);
        rs1 += __shfl_xor_sync(0xffffffffu, rs1, 2);
        l0 = l0 * al0 + rs0;
        l1 = l1 * al1 + rs1;
    }

    const float inv0 = 1.f / l0, inv1 = 1.f / l1;
    const int r0 = wid * 16 + (lane >> 2);
    const size_t zr0 = ((size_t)bh * SEQ + (size_t)qb * 128 + r0) * HDIM;
#pragma unroll
    for (int nt = 0; nt < 8; ++nt) {
        const int cc = nt * 8 + (lane & 3) * 2;
        *(uint32_t*)(g_Z + zr0 + cc) = packh2(o[nt][0] * inv0, o[nt][1] * inv0);
        *(uint32_t*)(g_Z + zr0 + 8 * HDIM + cc) = packh2(o[nt][2] * inv1, o[nt][3] * inv1);
    }
}

// ---------------- launch ----------------
extern "C" void kernel_launch(void* const* d_in, const int* in_sizes, int n_in,
                              void* d_out, int out_size)
{
    const float* X  = (const float*)d_in[0];
    const float* wq = (const float*)d_in[2];
    const float* bq = (const float*)d_in[3];
    const float* wk = (const float*)d_in[4];
    const float* bk = (const float*)d_in[5];
    const float* wv = (const float*)d_in[6];
    const float* bv = (const float*)d_in[7];
    const float* wo = (const float*)d_in[8];
    const float* bo = (const float*)d_in[9];
    float* out = (float*)d_out;

    __nv_bfloat16 *Xhi, *Xlo;
    __half *Xh;
    cudaGetSymbolAddress((void**)&Xhi, g_Xhi);
    cudaGetSymbolAddress((void**)&Xlo, g_Xlo);
    cudaGetSymbolAddress((void**)&Xh,  g_Xh);

    cudaFuncSetAttribute(attn_mma_kernel, cudaFuncAttributeMaxDynamicSharedMemorySize, ATTN_SMEM);
    cudaFuncSetAttribute(qk_mma_kernel,  cudaFuncAttributeMaxDynamicSharedMemorySize, GEMM_SMEM);
    cudaFuncSetAttribute(v_mma_kernel,   cudaFuncAttributeMaxDynamicSharedMemorySize, OGEMM_SMEM);
    cudaFuncSetAttribute(out_mma_kernel, cudaFuncAttributeMaxDynamicSharedMemorySize, OGEMM_SMEM);

    // split X into bf16 hi/lo + fp16 single; split+transpose weights
    cvt_split_kernel<<<(MROWS * EMB / 4) / 256, 256>>>(X, Xhi, Xlo, Xh);
    cvt_splitT_kernel<<<dim3(EMB / 32, EMB / 32, 4), 256>>>(wq, wk, wv, wo);

    // Q/K projections: bf16 3-term (z: 0=Q(xQSCALE) 1=K), per-head layout
    qk_mma_kernel<<<dim3(EMB / 128, MROWS / 128, 2), 256, GEMM_SMEM>>>(bq, bk);
    // V projection: fp16 2-term (X single x Wv hi/lo), per-head fp16 hi/lo
    v_mma_kernel<<<dim3(EMB / 128, MROWS / 128), 256, OGEMM_SMEM>>>(bv);

    // causal flash attention, diagonal-paired, producer/consumer -> g_Z (fp16)
    attn_mma_kernel<<<dim3(4, BATCH * HEADS), 256, ATTN_SMEM>>>();

    // output projection: fp16 2-term
    out_mma_kernel<<<dim3(EMB / 128, MROWS / 128), 256, OGEMM_SMEM>>>(bo, out);

    (void)in_sizes; (void)n_in; (void)out_size;
}

// round 16
// speedup vs baseline: 1.1819x; 1.1005x over previous
#include <cuda_runtime.h>
#include <cuda_bf16.h>
#include <cuda_fp16.h>
#include <cstdint>

// Problem constants
#define BATCH   4
#define SEQ     1024
#define EMB     1024
#define HEADS   16
#define HDIM    64
#define MROWS   (BATCH * SEQ)      // 4096

// ---------------- scratch (16B-aligned for cp.async) ----------------
__device__ __align__(256) __nv_bfloat16 g_Xhi[MROWS * EMB];
__device__ __align__(256) __nv_bfloat16 g_Xlo[MROWS * EMB];
__device__ __align__(256) __half       g_Xh [MROWS * EMB];   // X single fp16
// Q/K in per-head layout [B, H, S, HDIM], bf16 hi/lo; V single fp16
__device__ __align__(256) __nv_bfloat16 g_Qhi[MROWS * EMB];
__device__ __align__(256) __nv_bfloat16 g_Qlo[MROWS * EMB];
__device__ __align__(256) __nv_bfloat16 g_Khi[MROWS * EMB];
__device__ __align__(256) __nv_bfloat16 g_Klo[MROWS * EMB];
__device__ __align__(256) __half       g_V  [MROWS * EMB];
// Z single fp16
__device__ __align__(256) __half       g_Z[MROWS * EMB];
// wq,wk transposed [N,K] bf16 hi/lo; wv fp16 hi/lo; wo single fp16
__device__ __align__(256) __nv_bfloat16 g_Whi[2 * EMB * EMB];
__device__ __align__(256) __nv_bfloat16 g_Wlo[2 * EMB * EMB];
__device__ __align__(256) __half       g_WVhi[EMB * EMB];
__device__ __align__(256) __half       g_WVlo[EMB * EMB];
__device__ __align__(256) __half       g_WOh[EMB * EMB];

// ================= PTX helpers (sm_80+ subset only) =============
__device__ __forceinline__ uint32_t smem_u32(const void* p) {
    uint32_t a;
    asm("{ .reg .u64 t; cvta.to.shared.u64 t, %1; cvt.u32.u64 %0, t; }" : "=r"(a) : "l"(p));
    return a;
}

__device__ __forceinline__ void cp_async16(uint32_t saddr, const void* gaddr) {
    asm volatile("cp.async.cg.shared.global [%0], [%1], 16;" :: "r"(saddr), "l"(gaddr));
}
#define CP_COMMIT()  asm volatile("cp.async.commit_group;" ::: "memory")
template <int N>
__device__ __forceinline__ void cp_wait() {
    asm volatile("cp.async.wait_group %0;" :: "n"(N) : "memory");
}

#define BAR_ARRIVE(id, cnt) \
    asm volatile("bar.arrive %0, %1;" :: "r"((int)(id)), "r"((int)(cnt)) : "memory")
#define BAR_SYNC_N(id, cnt) \
    asm volatile("bar.sync %0, %1;" :: "r"((int)(id)), "r"((int)(cnt)) : "memory")

__device__ __forceinline__ void ldmatrix_x4(uint32_t (&r)[4], uint32_t addr) {
    asm volatile("ldmatrix.sync.aligned.m8n8.x4.shared.b16 {%0,%1,%2,%3}, [%4];"
                 : "=r"(r[0]), "=r"(r[1]), "=r"(r[2]), "=r"(r[3]) : "r"(addr));
}
__device__ __forceinline__ void ldmatrix_x4_trans(uint32_t (&r)[4], uint32_t addr) {
    asm volatile("ldmatrix.sync.aligned.m8n8.x4.trans.shared.b16 {%0,%1,%2,%3}, [%4];"
                 : "=r"(r[0]), "=r"(r[1]), "=r"(r[2]), "=r"(r[3]) : "r"(addr));
}

__device__ __forceinline__ void mma_16816(float (&d)[4], const uint32_t (&a)[4],
                                          uint32_t b0, uint32_t b1) {
    asm volatile(
        "mma.sync.aligned.m16n8k16.row.col.f32.bf16.bf16.f32 "
        "{%0,%1,%2,%3}, {%4,%5,%6,%7}, {%8,%9}, {%0,%1,%2,%3};"
        : "+f"(d[0]), "+f"(d[1]), "+f"(d[2]), "+f"(d[3])
        : "r"(a[0]), "r"(a[1]), "r"(a[2]), "r"(a[3]), "r"(b0), "r"(b1));
}
__device__ __forceinline__ void mma_16816_f16(float (&d)[4], const uint32_t (&a)[4],
                                              uint32_t b0, uint32_t b1) {
    asm volatile(
        "mma.sync.aligned.m16n8k16.row.col.f32.f16.f16.f32 "
        "{%0,%1,%2,%3}, {%4,%5,%6,%7}, {%8,%9}, {%0,%1,%2,%3};"
        : "+f"(d[0]), "+f"(d[1]), "+f"(d[2]), "+f"(d[3])
        : "r"(a[0]), "r"(a[1]), "r"(a[2]), "r"(a[3]), "r"(b0), "r"(b1));
}

// fp32 pair -> packed bf16x2 hi + lo
__device__ __forceinline__ void split2(float x, float y, uint32_t& hi, uint32_t& lo) {
    __nv_bfloat16 hx = __float2bfloat16(x);
    __nv_bfloat16 hy = __float2bfloat16(y);
    __nv_bfloat16 lx = __float2bfloat16(x - __bfloat162float(hx));
    __nv_bfloat16 ly = __float2bfloat16(y - __bfloat162float(hy));
    __nv_bfloat162 hp(hx, hy), lp(lx, ly);
    hi = *(uint32_t*)&hp;
    lo = *(uint32_t*)&lp;
}
__device__ __forceinline__ uint32_t packh2(float x, float y) {
    __half2 h = __floats2half2_rn(x, y);
    return *(uint32_t*)&h;
}

// ================= conversion kernels =================
__global__ __launch_bounds__(256) void cvt_split_kernel(
    const float* __restrict__ src, __nv_bfloat16* __restrict__ hi,
    __nv_bfloat16* __restrict__ lo, __half* __restrict__ h16)
{
    int i = blockIdx.x * blockDim.x + threadIdx.x;     // one float4 each
    float4 v = ((const float4*)src)[i];
    uint32_t h0, l0, h1, l1;
    split2(v.x, v.y, h0, l0);
    split2(v.z, v.w, h1, l1);
    ((uint2*)hi)[i] = make_uint2(h0, h1);
    ((uint2*)lo)[i] = make_uint2(l0, l1);
    ((uint2*)h16)[i] = make_uint2(packh2(v.x, v.y), packh2(v.z, v.w));
}

// W [K,N] fp32 -> WT [N,K]. z<2: bf16 hi/lo (wq,wk); z==2: fp16 hi/lo wv;
// z==3: fp16 single wo.
__global__ __launch_bounds__(256) void cvt_splitT_kernel(
    const float* __restrict__ w0, const float* __restrict__ w1,
    const float* __restrict__ w2, const float* __restrict__ w3)
{
    __shared__ float t[32][33];
    const int z = blockIdx.z;
    const float* W = (z == 0) ? w0 : (z == 1) ? w1 : (z == 2) ? w2 : w3;
    const int bx = blockIdx.x * 32;   // N base
    const int by = blockIdx.y * 32;   // K base
    const int tx = threadIdx.x & 31;
    const int ty = threadIdx.x >> 5;  // 0..7
    for (int i = ty; i < 32; i += 8)
        t[i][tx] = W[(size_t)(by + i) * EMB + bx + tx];
    __syncthreads();
    if (z < 2) {
        __nv_bfloat16* hiT = g_Whi + (size_t)z * EMB * EMB;
        __nv_bfloat16* loT = g_Wlo + (size_t)z * EMB * EMB;
        for (int i = ty; i < 32; i += 8) {
            float v = t[tx][i];
            __nv_bfloat16 h = __float2bfloat16(v);
            __nv_bfloat16 l = __float2bfloat16(v - __bfloat162float(h));
            hiT[(size_t)(bx + i) * EMB + by + tx] = h;
            loT[(size_t)(bx + i) * EMB + by + tx] = l;
        }
    } else if (z == 2) {
        for (int i = ty; i < 32; i += 8) {
            float v = t[tx][i];
            __half h = __float2half_rn(v);
            __half l = __float2half_rn(v - __half2float(h));
            g_WVhi[(size_t)(bx + i) * EMB + by + tx] = h;
            g_WVlo[(size_t)(bx + i) * EMB + by + tx] = l;
        }
    } else {
        for (int i = ty; i < 32; i += 8)
            g_WOh[(size_t)(bx + i) * EMB + by + tx] = __float2half_rn(t[tx][i]);
    }
}

// ================= HMMA bf16x3 Q/K GEMM (R12 shape) =================
#define BK          32
#define NCHUNK      (EMB / BK)              // 32
#define SA          40                       // smem row stride (elems)
#define SPLIT_BYTES (128 * SA * 2)          // 10240
#define STAGE_BYTES (4 * SPLIT_BYTES)       // 40960
#define GEMM_SMEM   (2 * STAGE_BYTES)       // 81920

// Q pre-scale: 1/16^0.25 * log2(e)  (softmax done in exp2 domain)
#define QSCALE (0.5f * 1.4426950408889634f)

__device__ __forceinline__ void load_stage_async(
    uint32_t smb, const __nv_bfloat16* __restrict__ Ahi, const __nv_bfloat16* __restrict__ Alo,
    const __nv_bfloat16* __restrict__ Bhi, const __nv_bfloat16* __restrict__ Blo,
    int mbase, int nbase, int k0, int buf, int tid)
{
    const __nv_bfloat16* gsrc[4] = {
        Ahi + (size_t)mbase * EMB + k0, Alo + (size_t)mbase * EMB + k0,
        Bhi + (size_t)nbase * EMB + k0, Blo + (size_t)nbase * EMB + k0 };
    const uint32_t sbase = smb + buf * STAGE_BYTES;
#pragma unroll
    for (int m = 0; m < 4; ++m) {
#pragma unroll
        for (int i = 0; i < 2; ++i) {
            int idx = tid + i * 256;
            int r = idx >> 2, seg = idx & 3;
            uint32_t sa = sbase + m * SPLIT_BYTES + (r * SA + seg * 8) * 2;
            cp_async16(sa, gsrc[m] + (size_t)r * EMB + seg * 8);
        }
    }
}

// mode 0: Q (bf16 split, xQSCALE); mode 1: K (bf16 split)
__global__ __launch_bounds__(256, 2)
void qk_mma_kernel(const float* __restrict__ bq, const float* __restrict__ bk)
{
    extern __shared__ char sm[];
    const uint32_t smb = smem_u32(sm);
    const int tid  = threadIdx.x;
    const int wid  = tid >> 5;
    const int lane = tid & 31;
    const int mbase = blockIdx.y * 128;
    const int nbase = blockIdx.x * 128;
    const int mode = blockIdx.z;

    const __nv_bfloat16* Bh = g_Whi + (size_t)mode * EMB * EMB;
    const __nv_bfloat16* Bl = g_Wlo + (size_t)mode * EMB * EMB;
    const float* bias = (mode == 0) ? bq : bk;

    const int wm = (wid & 1) * 64;
    const int wn = (wid >> 1) * 32;

    float acc[4][4][4];
#pragma unroll
    for (int mi = 0; mi < 4; ++mi)
#pragma unroll
        for (int ni = 0; ni < 4; ++ni)
#pragma unroll
            for (int e = 0; e < 4; ++e) acc[mi][ni][e] = 0.f;

    const int a_row = (lane & 15);
    const int a_koff = (lane >> 4) * 8;
    const int b_row = (lane & 7) + ((lane >> 4) * 8);
    const int b_koff = ((lane >> 3) & 1) * 8;

    load_stage_async(smb, g_Xhi, g_Xlo, Bh, Bl, mbase, nbase, 0, 0, tid);
    CP_COMMIT();

    for (int ck = 0; ck < NCHUNK; ++ck) {
        const int buf = ck & 1;
        cp_wait<0>();
        __syncthreads();
        if (ck + 1 < NCHUNK) {
            load_stage_async(smb, g_Xhi, g_Xlo, Bh, Bl, mbase, nbase, (ck + 1) * BK, buf ^ 1, tid);
            CP_COMMIT();
        }

        const uint32_t sAhi = smb + buf * STAGE_BYTES;
        const uint32_t sAlo = sAhi + SPLIT_BYTES;
        const uint32_t sBhi = sAhi + 2 * SPLIT_BYTES;
        const uint32_t sBlo = sAhi + 3 * SPLIT_BYTES;

#pragma unroll
        for (int ks = 0; ks < 2; ++ks) {
            const int k0 = ks * 16;
            uint32_t ahi[4][4], alo[4][4];
#pragma unroll
            for (int mi = 0; mi < 4; ++mi) {
                uint32_t off = ((wm + mi * 16 + a_row) * SA + k0 + a_koff) * 2;
                ldmatrix_x4(ahi[mi], sAhi + off);
                ldmatrix_x4(alo[mi], sAlo + off);
            }
            uint32_t bhi[2][4], blo[2][4];
#pragma unroll
            for (int bi = 0; bi < 2; ++bi) {
                uint32_t off = ((wn + bi * 16 + b_row) * SA + k0 + b_koff) * 2;
                ldmatrix_x4(bhi[bi], sBhi + off);
                ldmatrix_x4(blo[bi], sBlo + off);
            }
#pragma unroll
            for (int mi = 0; mi < 4; ++mi)
#pragma unroll
                for (int ni = 0; ni < 4; ++ni) {
                    const int g = ni >> 1, h = (ni & 1) * 2;
                    mma_16816(acc[mi][ni], ahi[mi], bhi[g][h], bhi[g][h + 1]);
                }
#pragma unroll
            for (int mi = 0; mi < 4; ++mi)
#pragma unroll
                for (int ni = 0; ni < 4; ++ni) {
                    const int g = ni >> 1, h = (ni & 1) * 2;
                    mma_16816(acc[mi][ni], ahi[mi], blo[g][h], blo[g][h + 1]);
                }
#pragma unroll
            for (int mi = 0; mi < 4; ++mi)
#pragma unroll
                for (int ni = 0; ni < 4; ++ni) {
                    const int g = ni >> 1, h = (ni & 1) * 2;
                    mma_16816(acc[mi][ni], alo[mi], bhi[g][h], bhi[g][h + 1]);
                }
        }
    }

    const int fr = lane >> 2;
    const int fc = (lane & 3) * 2;
    const float qscale = (mode == 0) ? QSCALE : 1.0f;
    __nv_bfloat16* Chi = (mode == 0) ? g_Qhi : g_Khi;
    __nv_bfloat16* Clo = (mode == 0) ? g_Qlo : g_Klo;
#pragma unroll
    for (int mi = 0; mi < 4; ++mi) {
#pragma unroll
        for (int ni = 0; ni < 4; ++ni) {
            const int col = nbase + wn + ni * 8 + fc;
            const float b0 = bias[col], b1 = bias[col + 1];
            const int row0 = mbase + wm + mi * 16 + fr;
            const float v0 = (acc[mi][ni][0] + b0) * qscale;
            const float v1 = (acc[mi][ni][1] + b1) * qscale;
            const float v2 = (acc[mi][ni][2] + b0) * qscale;
            const float v3 = (acc[mi][ni][3] + b1) * qscale;
            const int bb = row0 >> 10, ss = row0 & 1023;
            const int hh = col >> 6,  dd = col & 63;
            const size_t dst = (((size_t)bb * HEADS + hh) * SEQ + ss) * HDIM + dd;
            uint32_t h01, l01, h23, l23;
            split2(v0, v1, h01, l01);
            split2(v2, v3, h23, l23);
            *(uint32_t*)(Chi + dst)            = h01;
            *(uint32_t*)(Clo + dst)            = l01;
            *(uint32_t*)(Chi + dst + 8 * HDIM) = h23;
            *(uint32_t*)(Clo + dst + 8 * HDIM) = l23;
        }
    }
}

// ===== V projection: fp16 2-term (A=X single, B=Wv hi/lo), V single out ====
#define VSTAGE_BYTES (3 * SPLIT_BYTES)       // 30720: A, Bhi, Blo
#define VGEMM_SMEM   (2 * VSTAGE_BYTES)

__global__ __launch_bounds__(256, 2)
void v_mma_kernel(const float* __restrict__ bv)
{
    extern __shared__ char sm[];
    const uint32_t smb = smem_u32(sm);
    const int tid  = threadIdx.x;
    const int wid  = tid >> 5;
    const int lane = tid & 31;
    const int mbase = blockIdx.y * 128;
    const int nbase = blockIdx.x * 128;

    const int wm = (wid & 1) * 64;
    const int wn = (wid >> 1) * 32;

    float acc[4][4][4];
#pragma unroll
    for (int mi = 0; mi < 4; ++mi)
#pragma unroll
        for (int ni = 0; ni < 4; ++ni)
#pragma unroll
            for (int e = 0; e < 4; ++e) acc[mi][ni][e] = 0.f;

    const int a_row = (lane & 15);
    const int a_koff = (lane >> 4) * 8;
    const int b_row = (lane & 7) + ((lane >> 4) * 8);
    const int b_koff = ((lane >> 3) & 1) * 8;

    auto load_stage = [&](int k0, int buf) {
        const __half* gsrc[3] = {
            g_Xh   + (size_t)mbase * EMB + k0,
            g_WVhi + (size_t)nbase * EMB + k0,
            g_WVlo + (size_t)nbase * EMB + k0 };
        const uint32_t sbase = smb + buf * VSTAGE_BYTES;
#pragma unroll
        for (int m = 0; m < 3; ++m) {
#pragma unroll
            for (int i = 0; i < 2; ++i) {
                int idx = tid + i * 256;
                int r = idx >> 2, seg = idx & 3;
                uint32_t sa = sbase + m * SPLIT_BYTES + (r * SA + seg * 8) * 2;
                cp_async16(sa, gsrc[m] + (size_t)r * EMB + seg * 8);
            }
        }
    };

    load_stage(0, 0);
    CP_COMMIT();

    for (int ck = 0; ck < NCHUNK; ++ck) {
        const int buf = ck & 1;
        cp_wait<0>();
        __syncthreads();
        if (ck + 1 < NCHUNK) {
            load_stage((ck + 1) * BK, buf ^ 1);
            CP_COMMIT();
        }

        const uint32_t sA   = smb + buf * VSTAGE_BYTES;
        const uint32_t sBhi = sA + SPLIT_BYTES;
        const uint32_t sBlo = sA + 2 * SPLIT_BYTES;

#pragma unroll
        for (int ks = 0; ks < 2; ++ks) {
            const int k0 = ks * 16;
            uint32_t a[4][4];
#pragma unroll
            for (int mi = 0; mi < 4; ++mi) {
                uint32_t off = ((wm + mi * 16 + a_row) * SA + k0 + a_koff) * 2;
                ldmatrix_x4(a[mi], sA + off);
            }
            uint32_t bhi[2][4], blo[2][4];
#pragma unroll
            for (int bi = 0; bi < 2; ++bi) {
                uint32_t off = ((wn + bi * 16 + b_row) * SA + k0 + b_koff) * 2;
                ldmatrix_x4(bhi[bi], sBhi + off);
                ldmatrix_x4(blo[bi], sBlo + off);
            }
#pragma unroll
            for (int mi = 0; mi < 4; ++mi)
#pragma unroll
                for (int ni = 0; ni < 4; ++ni) {
                    const int g = ni >> 1, h = (ni & 1) * 2;
                    mma_16816_f16(acc[mi][ni], a[mi], bhi[g][h], bhi[g][h + 1]);
                }
#pragma unroll
            for (int mi = 0; mi < 4; ++mi)
#pragma unroll
                for (int ni = 0; ni < 4; ++ni) {
                    const int g = ni >> 1, h = (ni & 1) * 2;
                    mma_16816_f16(acc[mi][ni], a[mi], blo[g][h], blo[g][h + 1]);
                }
        }
    }

    const int fr = lane >> 2;
    const int fc = (lane & 3) * 2;
#pragma unroll
    for (int mi = 0; mi < 4; ++mi) {
#pragma unroll
        for (int ni = 0; ni < 4; ++ni) {
            const int col = nbase + wn + ni * 8 + fc;
            const float b0 = bv[col], b1 = bv[col + 1];
            const int row0 = mbase + wm + mi * 16 + fr;
            const int bb = row0 >> 10, ss = row0 & 1023;
            const int hh = col >> 6,  dd = col & 63;
            const size_t dst = (((size_t)bb * HEADS + hh) * SEQ + ss) * HDIM + dd;
            *(uint32_t*)(g_V + dst) =
                packh2(acc[mi][ni][0] + b0, acc[mi][ni][1] + b1);
            *(uint32_t*)(g_V + dst + 8 * HDIM) =
                packh2(acc[mi][ni][2] + b0, acc[mi][ni][3] + b1);
        }
    }
}

// ===== out projection: fp16 SINGLE-term (A=Z single, B=Wo single) =========
#define O2STAGE_BYTES (2 * SPLIT_BYTES)      // 20480: A, B
#define OGEMM_SMEM    (2 * O2STAGE_BYTES)

__global__ __launch_bounds__(256, 2)
void out_mma_kernel(const float* __restrict__ bo, float* __restrict__ out)
{
    extern __shared__ char sm[];
    const uint32_t smb = smem_u32(sm);
    const int tid  = threadIdx.x;
    const int wid  = tid >> 5;
    const int lane = tid & 31;
    const int mbase = blockIdx.y * 128;
    const int nbase = blockIdx.x * 128;

    const int wm = (wid & 1) * 64;
    const int wn = (wid >> 1) * 32;

    float acc[4][4][4];
#pragma unroll
    for (int mi = 0; mi < 4; ++mi)
#pragma unroll
        for (int ni = 0; ni < 4; ++ni)
#pragma unroll
            for (int e = 0; e < 4; ++e) acc[mi][ni][e] = 0.f;

    const int a_row = (lane & 15);
    const int a_koff = (lane >> 4) * 8;
    const int b_row = (lane & 7) + ((lane >> 4) * 8);
    const int b_koff = ((lane >> 3) & 1) * 8;

    auto load_stage = [&](int k0, int buf) {
        const __half* gsrc[2] = {
            g_Z   + (size_t)mbase * EMB + k0,
            g_WOh + (size_t)nbase * EMB + k0 };
        const uint32_t sbase = smb + buf * O2STAGE_BYTES;
#pragma unroll
        for (int m = 0; m < 2; ++m) {
#pragma unroll
            for (int i = 0; i < 2; ++i) {
                int idx = tid + i * 256;
                int r = idx >> 2, seg = idx & 3;
                uint32_t sa = sbase + m * SPLIT_BYTES + (r * SA + seg * 8) * 2;
                cp_async16(sa, gsrc[m] + (size_t)r * EMB + seg * 8);
            }
        }
    };

    load_stage(0, 0);
    CP_COMMIT();

    for (int ck = 0; ck < NCHUNK; ++ck) {
        const int buf = ck & 1;
        cp_wait<0>();
        __syncthreads();
        if (ck + 1 < NCHUNK) {
            load_stage((ck + 1) * BK, buf ^ 1);
            CP_COMMIT();
        }

        const uint32_t sA = smb + buf * O2STAGE_BYTES;
        const uint32_t sB = sA + SPLIT_BYTES;

#pragma unroll
        for (int ks = 0; ks < 2; ++ks) {
            const int k0 = ks * 16;
            uint32_t a[4][4];
#pragma unroll
            for (int mi = 0; mi < 4; ++mi) {
                uint32_t off = ((wm + mi * 16 + a_row) * SA + k0 + a_koff) * 2;
                ldmatrix_x4(a[mi], sA + off);
            }
            uint32_t b[2][4];
#pragma unroll
            for (int bi = 0; bi < 2; ++bi) {
                uint32_t off = ((wn + bi * 16 + b_row) * SA + k0 + b_koff) * 2;
                ldmatrix_x4(b[bi], sB + off);
            }
#pragma unroll
            for (int mi = 0; mi < 4; ++mi)
#pragma unroll
                for (int ni = 0; ni < 4; ++ni) {
                    const int g = ni >> 1, h = (ni & 1) * 2;
                    mma_16816_f16(acc[mi][ni], a[mi], b[g][h], b[g][h + 1]);
                }
        }
    }

    const int fr = lane >> 2;
    const int fc = (lane & 3) * 2;
#pragma unroll
    for (int mi = 0; mi < 4; ++mi) {
#pragma unroll
        for (int ni = 0; ni < 4; ++ni) {
            const int col = nbase + wn + ni * 8 + fc;
            const float b0 = bo[col], b1 = bo[col + 1];
            const int row0 = mbase + wm + mi * 16 + fr;
            float* p0 = out + (size_t)row0 * EMB + col;
            float* p1 = out + (size_t)(row0 + 8) * EMB + col;
            p0[0] = acc[mi][ni][0] + b0;
            p0[1] = acc[mi][ni][1] + b1;
            p1[0] = acc[mi][ni][2] + b0;
            p1[1] = acc[mi][ni][3] + b1;
        }
    }
}

// ================= Flash attention (V single fp16, PV 1-term) ==============
#define ASTR 72
#define Q_BYTES    (128 * ASTR * 2)          // 18432 per split
#define KVBUF      (3 * 64 * ASTR * 2)       // 27648: Kh, Kl, Vh
#define ATTN_SMEM  (2 * Q_BYTES + 2 * KVBUF) // 92160
#define ATTN_G     18
#define BARCNT     320
#define NBAR_E0    1
#define NBAR_E1    2
#define NBAR_F0    3
#define NBAR_F1    4

__device__ __forceinline__ void attn_load_kv64(uint32_t kvbase, size_t gbase,
                                               int jb, int tid64)
{
#pragma unroll
    for (int i = 0; i < 8; ++i) {
        int idx = tid64 + i * 64;                // 0..511
        int r = idx >> 3, seg = idx & 7;
        const size_t g = gbase + (size_t)(jb * 64 + r) * HDIM + seg * 8;
        const uint32_t so = (r * ASTR + seg * 8) * 2;
        cp_async16(kvbase + so,                  g_Khi + g);
        cp_async16(kvbase + 64 * ASTR * 2 + so,  g_Klo + g);
        cp_async16(kvbase + 128 * ASTR * 2 + so, g_V + g);
    }
}

__device__ __forceinline__ void attn_load_q(uint32_t uQh, uint32_t uQl,
                                            size_t gbase, int qb, int tid)
{
#pragma unroll
    for (int i = 0; i < 4; ++i) {
        int idx = tid + i * 256;
        int r = idx >> 3, seg = idx & 7;
        const size_t g = gbase + (size_t)(qb * 128 + r) * HDIM + seg * 8;
        const uint32_t so = (r * ASTR + seg * 8) * 2;
        cp_async16(uQh + so, g_Qhi + g);
        cp_async16(uQl + so, g_Qlo + g);
    }
}

__global__ __launch_bounds__(256, 2) void attn_mma_kernel()
{
    extern __shared__ char smraw[];
    const uint32_t uQh  = smem_u32(smraw);
    const uint32_t uQl  = uQh + Q_BYTES;
    const uint32_t uKV0 = uQl + Q_BYTES;

    const int tid = threadIdx.x, wid = tid >> 5, lane = tid & 31;
    const int pp = blockIdx.x;               // 0..3 (pair index)
    const int bh = blockIdx.y;               // 0..63
    const size_t gbase = (size_t)bh * SEQ * HDIM;
    const int qa = 7 - pp;
    const int cb = 2 * qa + 2;               // tiles consumed by first q-tile

    attn_load_q(uQh, uQl, gbase, qa, tid);
    CP_COMMIT();
    cp_wait<0>();
    __syncthreads();                         // Q visible

    if (wid < 2) {
        attn_load_kv64(uKV0, gbase, 0, tid);
        CP_COMMIT();
        attn_load_kv64(uKV0 + KVBUF, gbase, 1, tid);
        CP_COMMIT();
        cp_wait<1>();                        // tile 0 complete
        BAR_ARRIVE(NBAR_F0, BARCNT);
    }

    float o[8][4];
#pragma unroll
    for (int nt = 0; nt < 8; ++nt)
#pragma unroll
        for (int e = 0; e < 4; ++e) o[nt][e] = 0.f;
    float m0 = -1e30f, m1 = -1e30f, l0 = 0.f, l1 = 0.f;

    int qb = qa;
    int r0g = qb * 128 + wid * 16 + (lane >> 2);

    const int a_row = lane & 15;
    const int a_koff = (lane >> 4) * 8;
    const int b_row = (lane & 7) + ((lane >> 4) * 8);
    const int b_koff = ((lane >> 3) & 1) * 8;

    for (int c = 0; c < ATTN_G; ++c) {
        if (c == cb) {
            const float i0 = 1.f / l0, i1 = 1.f / l1;
            const int r0 = wid * 16 + (lane >> 2);
            const size_t zr0 = ((size_t)bh * SEQ + (size_t)qb * 128 + r0) * HDIM;
#pragma unroll
            for (int nt = 0; nt < 8; ++nt) {
                const int cc = nt * 8 + (lane & 3) * 2;
                *(uint32_t*)(g_Z + zr0 + cc) = packh2(o[nt][0] * i0, o[nt][1] * i0);
                *(uint32_t*)(g_Z + zr0 + 8 * HDIM + cc) = packh2(o[nt][2] * i1, o[nt][3] * i1);
            }
#pragma unroll
            for (int nt = 0; nt < 8; ++nt)
#pragma unroll
                for (int e = 0; e < 4; ++e) o[nt][e] = 0.f;
            m0 = -1e30f; m1 = -1e30f; l0 = 0.f; l1 = 0.f;
            qb = pp;
            r0g = qb * 128 + wid * 16 + (lane >> 2);
            __syncthreads();
            attn_load_q(uQh, uQl, gbase, qb, tid);
            CP_COMMIT();
            cp_wait<0>();
            __syncthreads();
        }

        BAR_SYNC_N((c & 1) ? NBAR_F1 : NBAR_F0, BARCNT);
        const uint32_t kvb = uKV0 + (c & 1) * KVBUF;
        const uint32_t uKh = kvb;
        const uint32_t uKl = kvb + 64 * ASTR * 2;
        const uint32_t uVh = kvb + 128 * ASTR * 2;
        const int jb = (c < cb) ? c : c - cb;

        float s[8][4];
#pragma unroll
        for (int nt = 0; nt < 8; ++nt)
#pragma unroll
            for (int e = 0; e < 4; ++e) s[nt][e] = 0.f;

#pragma unroll
        for (int ks = 0; ks < 4; ++ks) {
            uint32_t qh[4], ql[4];
            {
                uint32_t off = ((wid * 16 + a_row) * ASTR + ks * 16 + a_koff) * 2;
                ldmatrix_x4(qh, uQh + off);
                ldmatrix_x4(ql, uQl + off);
            }
            uint32_t kh[4][4], kl[4][4];
#pragma unroll
            for (int g = 0; g < 4; ++g) {
                uint32_t off = ((g * 16 + b_row) * ASTR + ks * 16 + b_koff) * 2;
                ldmatrix_x4(kh[g], uKh + off);
                ldmatrix_x4(kl[g], uKl + off);
            }
#pragma unroll
            for (int g = 0; g < 4; ++g)
#pragma unroll
                for (int hh = 0; hh < 2; ++hh)
                    mma_16816(s[2 * g + hh], qh, kh[g][hh * 2], kh[g][hh * 2 + 1]);
#pragma unroll
            for (int g = 0; g < 4; ++g)
#pragma unroll
                for (int hh = 0; hh < 2; ++hh)
                    mma_16816(s[2 * g + hh], qh, kl[g][hh * 2], kl[g][hh * 2 + 1]);
#pragma unroll
            for (int g = 0; g < 4; ++g)
#pragma unroll
                for (int hh = 0; hh < 2; ++hh)
                    mma_16816(s[2 * g + hh], ql, kh[g][hh * 2], kh[g][hh * 2 + 1]);
        }

        const bool needmask = (jb >= 2 * qb);
        float mx0 = -1e30f, mx1 = -1e30f;
#pragma unroll
        for (int nt = 0; nt < 8; ++nt) {
            if (needmask) {
                const int cc = jb * 64 + nt * 8 + (lane & 3) * 2;
                s[nt][0] = (cc     <= r0g)     ? s[nt][0] : -1e30f;
                s[nt][1] = (cc + 1 <= r0g)     ? s[nt][1] : -1e30f;
                s[nt][2] = (cc     <= r0g + 8) ? s[nt][2] : -1e30f;
                s[nt][3] = (cc + 1 <= r0g + 8) ? s[nt][3] : -1e30f;
            }
            mx0 = fmaxf(mx0, fmaxf(s[nt][0], s[nt][1]));
            mx1 = fmaxf(mx1, fmaxf(s[nt][2], s[nt][3]));
        }
        mx0 = fmaxf(mx0, __shfl_xor_sync(0xffffffffu, mx0, 1));
        mx0 = fmaxf(mx0, __shfl_xor_sync(0xffffffffu, mx0, 2));
        mx1 = fmaxf(mx1, __shfl_xor_sync(0xffffffffu, mx1, 1));
        mx1 = fmaxf(mx1, __shfl_xor_sync(0xffffffffu, mx1, 2));

        const float nm0 = fmaxf(m0, mx0), nm1 = fmaxf(m1, mx1);
        const float al0 = exp2f(m0 - nm0), al1 = exp2f(m1 - nm1);
        m0 = nm0; m1 = nm1;

#pragma unroll
        for (int nt = 0; nt < 8; ++nt) {
            o[nt][0] *= al0; o[nt][1] *= al0;
            o[nt][2] *= al1; o[nt][3] *= al1;
        }

        float rs0 = 0.f, rs1 = 0.f;
#pragma unroll
        for (int ks = 0; ks < 4; ++ks) {
            float* sa = s[2 * ks];
            float* sb = s[2 * ks + 1];
            sa[0] = exp2f(sa[0] - m0);
            sa[1] = exp2f(sa[1] - m0);
            sa[2] = exp2f(sa[2] - m1);
            sa[3] = exp2f(sa[3] - m1);
            sb[0] = exp2f(sb[0] - m0);
            sb[1] = exp2f(sb[1] - m0);
            sb[2] = exp2f(sb[2] - m1);
            sb[3] = exp2f(sb[3] - m1);
            rs0 += sa[0] + sa[1] + sb[0] + sb[1];
            rs1 += sa[2] + sa[3] + sb[2] + sb[3];

            uint32_t ph[4];
            ph[0] = packh2(sa[0], sa[1]);
            ph[1] = packh2(sa[2], sa[3]);
            ph[2] = packh2(sb[0], sb[1]);
            ph[3] = packh2(sb[2], sb[3]);

            uint32_t vh[4][4];
#pragma unroll
            for (int dg = 0; dg < 4; ++dg) {
                uint32_t off = (((lane & 15) + ks * 16) * ASTR + dg * 16 + (lane >> 4) * 8) * 2;
                ldmatrix_x4_trans(vh[dg], uVh + off);
            }
#pragma unroll
            for (int dg = 0; dg < 4; ++dg)
#pragma unroll
                for (int hh = 0; hh < 2; ++hh)
                    mma_16816_f16(o[2 * dg + hh], ph, vh[dg][hh * 2], vh[dg][hh * 2 + 1]);
        }

        BAR_ARRIVE((c & 1) ? NBAR_E1 : NBAR_E0, BARCNT);

        if (wid < 2) {
            const bool refill = (c + 2 < ATTN_G);
            if (refill) {
                BAR_SYNC_N((c & 1) ? NBAR_E1 : NBAR_E0, BARCNT);
                const int g = c + 2;
                const int gj = (g < cb) ? g : g - cb;
                attn_load_kv64(uKV0 + (g & 1) * KVBUF, gbase, gj, tid);
                CP_COMMIT();
            }
            if (c + 1 < ATTN_G) {
                if (refill) cp_wait<1>();
                else        cp_wait<0>();
                BAR_ARRIVE(((c + 1) & 1) ? NBAR_F1 : NBAR_F0, BARCNT);
            }
        }

        rs0 += __shfl_xor_sync(0xffffffffu, rs0, 1);
        rs0 += __shfl_xor_sync(0xffffffffu, rs0, 2);
        rs1 += __shfl_xor_sync(0xffffffffu, rs1, 1);
        rs1 += __shfl_xor_sync(0xffffffffu, rs1, 2);
        l0 = l0 * al0 + rs0;
        l1 = l1 * al1 + rs1;
    }

    const float inv0 = 1.f / l0, inv1 = 1.f / l1;
    const int r0 = wid * 16 + (lane >> 2);
    const size_t zr0 = ((size_t)bh * SEQ + (size_t)qb * 128 + r0) * HDIM;
#pragma unroll
    for (int nt = 0; nt < 8; ++nt) {
        const int cc = nt * 8 + (lane & 3) * 2;
        *(uint32_t*)(g_Z + zr0 + cc) = packh2(o[nt][0] * inv0, o[nt][1] * inv0);
        *(uint32_t*)(g_Z + zr0 + 8 * HDIM + cc) = packh2(o[nt][2] * inv1, o[nt][3] * inv1);
    }
}

// ---------------- launch ----------------
extern "C" void kernel_launch(void* const* d_in, const int* in_sizes, int n_in,
                              void* d_out, int out_size)
{
    const float* X  = (const float*)d_in[0];
    const float* wq = (const float*)d_in[2];
    const float* bq = (const float*)d_in[3];
    const float* wk = (const float*)d_in[4];
    const float* bk = (const float*)d_in[5];
    const float* wv = (const float*)d_in[6];
    const float* bv = (const float*)d_in[7];
    const float* wo = (const float*)d_in[8];
    const float* bo = (const float*)d_in[9];
    float* out = (float*)d_out;

    __nv_bfloat16 *Xhi, *Xlo;
    __half *Xh;
    cudaGetSymbolAddress((void**)&Xhi, g_Xhi);
    cudaGetSymbolAddress((void**)&Xlo, g_Xlo);
    cudaGetSymbolAddress((void**)&Xh,  g_Xh);

    cudaFuncSetAttribute(attn_mma_kernel, cudaFuncAttributeMaxDynamicSharedMemorySize, ATTN_SMEM);
    cudaFuncSetAttribute(qk_mma_kernel,  cudaFuncAttributeMaxDynamicSharedMemorySize, GEMM_SMEM);
    cudaFuncSetAttribute(v_mma_kernel,   cudaFuncAttributeMaxDynamicSharedMemorySize, VGEMM_SMEM);
    cudaFuncSetAttribute(out_mma_kernel, cudaFuncAttributeMaxDynamicSharedMemorySize, OGEMM_SMEM);

    // split X into bf16 hi/lo + fp16 single; split+transpose weights
    cvt_split_kernel<<<(MROWS * EMB / 4) / 256, 256>>>(X, Xhi, Xlo, Xh);
    cvt_splitT_kernel<<<dim3(EMB / 32, EMB / 32, 4), 256>>>(wq, wk, wv, wo);

    // Q/K projections: bf16 3-term (z: 0=Q(xQSCALE) 1=K), per-head layout
    qk_mma_kernel<<<dim3(EMB / 128, MROWS / 128, 2), 256, GEMM_SMEM>>>(bq, bk);
    // V projection: fp16 2-term -> V single fp16, per-head layout
    v_mma_kernel<<<dim3(EMB / 128, MROWS / 128), 256, VGEMM_SMEM>>>(bv);

    // causal flash attention (PV single-term) -> g_Z (fp16)
    attn_mma_kernel<<<dim3(4, BATCH * HEADS), 256, ATTN_SMEM>>>();

    // output projection: fp16 single-term
    out_mma_kernel<<<dim3(EMB / 128, MROWS / 128), 256, OGEMM_SMEM>>>(bo, out);

    (void)in_sizes; (void)n_in; (void)out_size;
}

// round 17
// speedup vs baseline: 1.2500x; 1.0576x over previous
#include <cuda_runtime.h>
#include <cuda_bf16.h>
#include <cuda_fp16.h>
#include <cstdint>

// Problem constants
#define BATCH   4
#define SEQ     1024
#define EMB     1024
#define HEADS   16
#define HDIM    64
#define MROWS   (BATCH * SEQ)      // 4096

// ---------------- scratch (16B-aligned for cp.async) ----------------
__device__ __align__(256) __nv_bfloat16 g_Xhi[MROWS * EMB];
__device__ __align__(256) __nv_bfloat16 g_Xlo[MROWS * EMB];
__device__ __align__(256) __half       g_Xh [MROWS * EMB];   // X single fp16
// Q/K in per-head layout [B, H, S, HDIM], bf16 hi/lo; V single fp16
__device__ __align__(256) __nv_bfloat16 g_Qhi[MROWS * EMB];
__device__ __align__(256) __nv_bfloat16 g_Qlo[MROWS * EMB];
__device__ __align__(256) __nv_bfloat16 g_Khi[MROWS * EMB];
__device__ __align__(256) __nv_bfloat16 g_Klo[MROWS * EMB];
__device__ __align__(256) __half       g_V  [MROWS * EMB];
// Z single fp16
__device__ __align__(256) __half       g_Z[MROWS * EMB];
// wq,wk transposed [N,K] bf16 hi/lo; wv single fp16; wo single fp16
__device__ __align__(256) __nv_bfloat16 g_Whi[2 * EMB * EMB];
__device__ __align__(256) __nv_bfloat16 g_Wlo[2 * EMB * EMB];
__device__ __align__(256) __half       g_WVh[EMB * EMB];
__device__ __align__(256) __half       g_WOh[EMB * EMB];

// ================= PTX helpers (sm_80+ subset only) =============
__device__ __forceinline__ uint32_t smem_u32(const void* p) {
    uint32_t a;
    asm("{ .reg .u64 t; cvta.to.shared.u64 t, %1; cvt.u32.u64 %0, t; }" : "=r"(a) : "l"(p));
    return a;
}

__device__ __forceinline__ void cp_async16(uint32_t saddr, const void* gaddr) {
    asm volatile("cp.async.cg.shared.global [%0], [%1], 16;" :: "r"(saddr), "l"(gaddr));
}
#define CP_COMMIT()  asm volatile("cp.async.commit_group;" ::: "memory")
template <int N>
__device__ __forceinline__ void cp_wait() {
    asm volatile("cp.async.wait_group %0;" :: "n"(N) : "memory");
}

#define BAR_ARRIVE(id, cnt) \
    asm volatile("bar.arrive %0, %1;" :: "r"((int)(id)), "r"((int)(cnt)) : "memory")
#define BAR_SYNC_N(id, cnt) \
    asm volatile("bar.sync %0, %1;" :: "r"((int)(id)), "r"((int)(cnt)) : "memory")

__device__ __forceinline__ void ldmatrix_x4(uint32_t (&r)[4], uint32_t addr) {
    asm volatile("ldmatrix.sync.aligned.m8n8.x4.shared.b16 {%0,%1,%2,%3}, [%4];"
                 : "=r"(r[0]), "=r"(r[1]), "=r"(r[2]), "=r"(r[3]) : "r"(addr));
}
__device__ __forceinline__ void ldmatrix_x4_trans(uint32_t (&r)[4], uint32_t addr) {
    asm volatile("ldmatrix.sync.aligned.m8n8.x4.trans.shared.b16 {%0,%1,%2,%3}, [%4];"
                 : "=r"(r[0]), "=r"(r[1]), "=r"(r[2]), "=r"(r[3]) : "r"(addr));
}

__device__ __forceinline__ void mma_16816(float (&d)[4], const uint32_t (&a)[4],
                                          uint32_t b0, uint32_t b1) {
    asm volatile(
        "mma.sync.aligned.m16n8k16.row.col.f32.bf16.bf16.f32 "
        "{%0,%1,%2,%3}, {%4,%5,%6,%7}, {%8,%9}, {%0,%1,%2,%3};"
        : "+f"(d[0]), "+f"(d[1]), "+f"(d[2]), "+f"(d[3])
        : "r"(a[0]), "r"(a[1]), "r"(a[2]), "r"(a[3]), "r"(b0), "r"(b1));
}
__device__ __forceinline__ void mma_16816_f16(float (&d)[4], const uint32_t (&a)[4],
                                              uint32_t b0, uint32_t b1) {
    asm volatile(
        "mma.sync.aligned.m16n8k16.row.col.f32.f16.f16.f32 "
        "{%0,%1,%2,%3}, {%4,%5,%6,%7}, {%8,%9}, {%0,%1,%2,%3};"
        : "+f"(d[0]), "+f"(d[1]), "+f"(d[2]), "+f"(d[3])
        : "r"(a[0]), "r"(a[1]), "r"(a[2]), "r"(a[3]), "r"(b0), "r"(b1));
}

// fp32 pair -> packed bf16x2 hi + lo
__device__ __forceinline__ void split2(float x, float y, uint32_t& hi, uint32_t& lo) {
    __nv_bfloat16 hx = __float2bfloat16(x);
    __nv_bfloat16 hy = __float2bfloat16(y);
    __nv_bfloat16 lx = __float2bfloat16(x - __bfloat162float(hx));
    __nv_bfloat16 ly = __float2bfloat16(y - __bfloat162float(hy));
    __nv_bfloat162 hp(hx, hy), lp(lx, ly);
    hi = *(uint32_t*)&hp;
    lo = *(uint32_t*)&lp;
}
__device__ __forceinline__ uint32_t packh2(float x, float y) {
    __half2 h = __floats2half2_rn(x, y);
    return *(uint32_t*)&h;
}

// ================= conversion kernels =================
__global__ __launch_bounds__(256) void cvt_split_kernel(
    const float* __restrict__ src, __nv_bfloat16* __restrict__ hi,
    __nv_bfloat16* __restrict__ lo, __half* __restrict__ h16)
{
    int i = blockIdx.x * blockDim.x + threadIdx.x;     // one float4 each
    float4 v = ((const float4*)src)[i];
    uint32_t h0, l0, h1, l1;
    split2(v.x, v.y, h0, l0);
    split2(v.z, v.w, h1, l1);
    ((uint2*)hi)[i] = make_uint2(h0, h1);
    ((uint2*)lo)[i] = make_uint2(l0, l1);
    ((uint2*)h16)[i] = make_uint2(packh2(v.x, v.y), packh2(v.z, v.w));
}

// W [K,N] fp32 -> WT [N,K]. z<2: bf16 hi/lo (wq,wk); z==2: fp16 single wv;
// z==3: fp16 single wo.
__global__ __launch_bounds__(256) void cvt_splitT_kernel(
    const float* __restrict__ w0, const float* __restrict__ w1,
    const float* __restrict__ w2, const float* __restrict__ w3)
{
    __shared__ float t[32][33];
    const int z = blockIdx.z;
    const float* W = (z == 0) ? w0 : (z == 1) ? w1 : (z == 2) ? w2 : w3;
    const int bx = blockIdx.x * 32;   // N base
    const int by = blockIdx.y * 32;   // K base
    const int tx = threadIdx.x & 31;
    const int ty = threadIdx.x >> 5;  // 0..7
    for (int i = ty; i < 32; i += 8)
        t[i][tx] = W[(size_t)(by + i) * EMB + bx + tx];
    __syncthreads();
    if (z < 2) {
        __nv_bfloat16* hiT = g_Whi + (size_t)z * EMB * EMB;
        __nv_bfloat16* loT = g_Wlo + (size_t)z * EMB * EMB;
        for (int i = ty; i < 32; i += 8) {
            float v = t[tx][i];
            __nv_bfloat16 h = __float2bfloat16(v);
            __nv_bfloat16 l = __float2bfloat16(v - __bfloat162float(h));
            hiT[(size_t)(bx + i) * EMB + by + tx] = h;
            loT[(size_t)(bx + i) * EMB + by + tx] = l;
        }
    } else {
        __half* dstT = (z == 2) ? g_WVh : g_WOh;
        for (int i = ty; i < 32; i += 8)
            dstT[(size_t)(bx + i) * EMB + by + tx] = __float2half_rn(t[tx][i]);
    }
}

// ================= HMMA bf16x3 Q/K GEMM (R12 shape) =================
#define BK          32
#define NCHUNK      (EMB / BK)              // 32
#define SA          40                       // smem row stride (elems)
#define SPLIT_BYTES (128 * SA * 2)          // 10240
#define STAGE_BYTES (4 * SPLIT_BYTES)       // 40960
#define GEMM_SMEM   (2 * STAGE_BYTES)       // 81920

// Q pre-scale: 1/16^0.25 * log2(e)  (softmax done in exp2 domain)
#define QSCALE (0.5f * 1.4426950408889634f)

__device__ __forceinline__ void load_stage_async(
    uint32_t smb, const __nv_bfloat16* __restrict__ Ahi, const __nv_bfloat16* __restrict__ Alo,
    const __nv_bfloat16* __restrict__ Bhi, const __nv_bfloat16* __restrict__ Blo,
    int mbase, int nbase, int k0, int buf, int tid)
{
    const __nv_bfloat16* gsrc[4] = {
        Ahi + (size_t)mbase * EMB + k0, Alo + (size_t)mbase * EMB + k0,
        Bhi + (size_t)nbase * EMB + k0, Blo + (size_t)nbase * EMB + k0 };
    const uint32_t sbase = smb + buf * STAGE_BYTES;
#pragma unroll
    for (int m = 0; m < 4; ++m) {
#pragma unroll
        for (int i = 0; i < 2; ++i) {
            int idx = tid + i * 256;
            int r = idx >> 2, seg = idx & 3;
            uint32_t sa = sbase + m * SPLIT_BYTES + (r * SA + seg * 8) * 2;
            cp_async16(sa, gsrc[m] + (size_t)r * EMB + seg * 8);
        }
    }
}

// mode 0: Q (bf16 split, xQSCALE); mode 1: K (bf16 split)
__global__ __launch_bounds__(256, 2)
void qk_mma_kernel(const float* __restrict__ bq, const float* __restrict__ bk)
{
    extern __shared__ char sm[];
    const uint32_t smb = smem_u32(sm);
    const int tid  = threadIdx.x;
    const int wid  = tid >> 5;
    const int lane = tid & 31;
    const int mbase = blockIdx.y * 128;
    const int nbase = blockIdx.x * 128;
    const int mode = blockIdx.z;

    const __nv_bfloat16* Bh = g_Whi + (size_t)mode * EMB * EMB;
    const __nv_bfloat16* Bl = g_Wlo + (size_t)mode * EMB * EMB;
    const float* bias = (mode == 0) ? bq : bk;

    const int wm = (wid & 1) * 64;
    const int wn = (wid >> 1) * 32;

    float acc[4][4][4];
#pragma unroll
    for (int mi = 0; mi < 4; ++mi)
#pragma unroll
        for (int ni = 0; ni < 4; ++ni)
#pragma unroll
            for (int e = 0; e < 4; ++e) acc[mi][ni][e] = 0.f;

    const int a_row = (lane & 15);
    const int a_koff = (lane >> 4) * 8;
    const int b_row = (lane & 7) + ((lane >> 4) * 8);
    const int b_koff = ((lane >> 3) & 1) * 8;

    load_stage_async(smb, g_Xhi, g_Xlo, Bh, Bl, mbase, nbase, 0, 0, tid);
    CP_COMMIT();

    for (int ck = 0; ck < NCHUNK; ++ck) {
        const int buf = ck & 1;
        cp_wait<0>();
        __syncthreads();
        if (ck + 1 < NCHUNK) {
            load_stage_async(smb, g_Xhi, g_Xlo, Bh, Bl, mbase, nbase, (ck + 1) * BK, buf ^ 1, tid);
            CP_COMMIT();
        }

        const uint32_t sAhi = smb + buf * STAGE_BYTES;
        const uint32_t sAlo = sAhi + SPLIT_BYTES;
        const uint32_t sBhi = sAhi + 2 * SPLIT_BYTES;
        const uint32_t sBlo = sAhi + 3 * SPLIT_BYTES;

#pragma unroll
        for (int ks = 0; ks < 2; ++ks) {
            const int k0 = ks * 16;
            uint32_t ahi[4][4], alo[4][4];
#pragma unroll
            for (int mi = 0; mi < 4; ++mi) {
                uint32_t off = ((wm + mi * 16 + a_row) * SA + k0 + a_koff) * 2;
                ldmatrix_x4(ahi[mi], sAhi + off);
                ldmatrix_x4(alo[mi], sAlo + off);
            }
            uint32_t bhi[2][4], blo[2][4];
#pragma unroll
            for (int bi = 0; bi < 2; ++bi) {
                uint32_t off = ((wn + bi * 16 + b_row) * SA + k0 + b_koff) * 2;
                ldmatrix_x4(bhi[bi], sBhi + off);
                ldmatrix_x4(blo[bi], sBlo + off);
            }
#pragma unroll
            for (int mi = 0; mi < 4; ++mi)
#pragma unroll
                for (int ni = 0; ni < 4; ++ni) {
                    const int g = ni >> 1, h = (ni & 1) * 2;
                    mma_16816(acc[mi][ni], ahi[mi], bhi[g][h], bhi[g][h + 1]);
                }
#pragma unroll
            for (int mi = 0; mi < 4; ++mi)
#pragma unroll
                for (int ni = 0; ni < 4; ++ni) {
                    const int g = ni >> 1, h = (ni & 1) * 2;
                    mma_16816(acc[mi][ni], ahi[mi], blo[g][h], blo[g][h + 1]);
                }
#pragma unroll
            for (int mi = 0; mi < 4; ++mi)
#pragma unroll
                for (int ni = 0; ni < 4; ++ni) {
                    const int g = ni >> 1, h = (ni & 1) * 2;
                    mma_16816(acc[mi][ni], alo[mi], bhi[g][h], bhi[g][h + 1]);
                }
        }
    }

    const int fr = lane >> 2;
    const int fc = (lane & 3) * 2;
    const float qscale = (mode == 0) ? QSCALE : 1.0f;
    __nv_bfloat16* Chi = (mode == 0) ? g_Qhi : g_Khi;
    __nv_bfloat16* Clo = (mode == 0) ? g_Qlo : g_Klo;
#pragma unroll
    for (int mi = 0; mi < 4; ++mi) {
#pragma unroll
        for (int ni = 0; ni < 4; ++ni) {
            const int col = nbase + wn + ni * 8 + fc;
            const float b0 = bias[col], b1 = bias[col + 1];
            const int row0 = mbase + wm + mi * 16 + fr;
            const float v0 = (acc[mi][ni][0] + b0) * qscale;
            const float v1 = (acc[mi][ni][1] + b1) * qscale;
            const float v2 = (acc[mi][ni][2] + b0) * qscale;
            const float v3 = (acc[mi][ni][3] + b1) * qscale;
            const int bb = row0 >> 10, ss = row0 & 1023;
            const int hh = col >> 6,  dd = col & 63;
            const size_t dst = (((size_t)bb * HEADS + hh) * SEQ + ss) * HDIM + dd;
            uint32_t h01, l01, h23, l23;
            split2(v0, v1, h01, l01);
            split2(v2, v3, h23, l23);
            *(uint32_t*)(Chi + dst)            = h01;
            *(uint32_t*)(Clo + dst)            = l01;
            *(uint32_t*)(Chi + dst + 8 * HDIM) = h23;
            *(uint32_t*)(Clo + dst + 8 * HDIM) = l23;
        }
    }
}

// ===== fp16 single-term GEMM body (A single, B single) ======================
#define H2STAGE_BYTES (2 * SPLIT_BYTES)      // 20480: A, B
#define HGEMM_SMEM    (2 * H2STAGE_BYTES)

// VOUT=true: epilogue writes per-head V single fp16. VOUT=false: f32 to out.
template <bool VOUT>
__device__ __forceinline__ void gemm_body_h1(
    const __half* __restrict__ A, const __half* __restrict__ B,
    const float* __restrict__ bias, float* __restrict__ outf)
{
    extern __shared__ char sm[];
    const uint32_t smb = smem_u32(sm);
    const int tid  = threadIdx.x;
    const int wid  = tid >> 5;
    const int lane = tid & 31;
    const int mbase = blockIdx.y * 128;
    const int nbase = blockIdx.x * 128;

    const int wm = (wid & 1) * 64;
    const int wn = (wid >> 1) * 32;

    float acc[4][4][4];
#pragma unroll
    for (int mi = 0; mi < 4; ++mi)
#pragma unroll
        for (int ni = 0; ni < 4; ++ni)
#pragma unroll
            for (int e = 0; e < 4; ++e) acc[mi][ni][e] = 0.f;

    const int a_row = (lane & 15);
    const int a_koff = (lane >> 4) * 8;
    const int b_row = (lane & 7) + ((lane >> 4) * 8);
    const int b_koff = ((lane >> 3) & 1) * 8;

    auto load_stage = [&](int k0, int buf) {
        const __half* gsrc[2] = {
            A + (size_t)mbase * EMB + k0,
            B + (size_t)nbase * EMB + k0 };
        const uint32_t sbase = smb + buf * H2STAGE_BYTES;
#pragma unroll
        for (int m = 0; m < 2; ++m) {
#pragma unroll
            for (int i = 0; i < 2; ++i) {
                int idx = tid + i * 256;
                int r = idx >> 2, seg = idx & 3;
                uint32_t sa = sbase + m * SPLIT_BYTES + (r * SA + seg * 8) * 2;
                cp_async16(sa, gsrc[m] + (size_t)r * EMB + seg * 8);
            }
        }
    };

    load_stage(0, 0);
    CP_COMMIT();

    for (int ck = 0; ck < NCHUNK; ++ck) {
        const int buf = ck & 1;
        cp_wait<0>();
        __syncthreads();
        if (ck + 1 < NCHUNK) {
            load_stage((ck + 1) * BK, buf ^ 1);
            CP_COMMIT();
        }

        const uint32_t sA = smb + buf * H2STAGE_BYTES;
        const uint32_t sB = sA + SPLIT_BYTES;

#pragma unroll
        for (int ks = 0; ks < 2; ++ks) {
            const int k0 = ks * 16;
            uint32_t a[4][4];
#pragma unroll
            for (int mi = 0; mi < 4; ++mi) {
                uint32_t off = ((wm + mi * 16 + a_row) * SA + k0 + a_koff) * 2;
                ldmatrix_x4(a[mi], sA + off);
            }
            uint32_t b[2][4];
#pragma unroll
            for (int bi = 0; bi < 2; ++bi) {
                uint32_t off = ((wn + bi * 16 + b_row) * SA + k0 + b_koff) * 2;
                ldmatrix_x4(b[bi], sB + off);
            }
#pragma unroll
            for (int mi = 0; mi < 4; ++mi)
#pragma unroll
                for (int ni = 0; ni < 4; ++ni) {
                    const int g = ni >> 1, h = (ni & 1) * 2;
                    mma_16816_f16(acc[mi][ni], a[mi], b[g][h], b[g][h + 1]);
                }
        }
    }

    const int fr = lane >> 2;
    const int fc = (lane & 3) * 2;
#pragma unroll
    for (int mi = 0; mi < 4; ++mi) {
#pragma unroll
        for (int ni = 0; ni < 4; ++ni) {
            const int col = nbase + wn + ni * 8 + fc;
            const float b0 = bias[col], b1 = bias[col + 1];
            const int row0 = mbase + wm + mi * 16 + fr;
            const float v0 = acc[mi][ni][0] + b0;
            const float v1 = acc[mi][ni][1] + b1;
            const float v2 = acc[mi][ni][2] + b0;
            const float v3 = acc[mi][ni][3] + b1;
            if (VOUT) {
                const int bb = row0 >> 10, ss = row0 & 1023;
                const int hh = col >> 6,  dd = col & 63;
                const size_t dst = (((size_t)bb * HEADS + hh) * SEQ + ss) * HDIM + dd;
                *(uint32_t*)(g_V + dst)            = packh2(v0, v1);
                *(uint32_t*)(g_V + dst + 8 * HDIM) = packh2(v2, v3);
            } else {
                float* p0 = outf + (size_t)row0 * EMB + col;
                float* p1 = outf + (size_t)(row0 + 8) * EMB + col;
                p0[0] = v0; p0[1] = v1;
                p1[0] = v2; p1[1] = v3;
            }
        }
    }
}

__global__ __launch_bounds__(256, 2)
void v_mma_kernel(const float* __restrict__ bv)
{
    gemm_body_h1<true>(g_Xh, g_WVh, bv, nullptr);
}

__global__ __launch_bounds__(256, 2)
void out_mma_kernel(const float* __restrict__ bo, float* __restrict__ out)
{
    gemm_body_h1<false>(g_Z, g_WOh, bo, out);
}

// ================= Flash attention (V single fp16, PV 1-term) ==============
#define ASTR 72
#define Q_BYTES    (128 * ASTR * 2)          // 18432 per split
#define KVBUF      (3 * 64 * ASTR * 2)       // 27648: Kh, Kl, Vh
#define ATTN_SMEM  (2 * Q_BYTES + 2 * KVBUF) // 92160
#define ATTN_G     18
#define BARCNT     320
#define NBAR_E0    1
#define NBAR_E1    2
#define NBAR_F0    3
#define NBAR_F1    4

__device__ __forceinline__ void attn_load_kv64(uint32_t kvbase, size_t gbase,
                                               int jb, int tid64)
{
#pragma unroll
    for (int i = 0; i < 8; ++i) {
        int idx = tid64 + i * 64;                // 0..511
        int r = idx >> 3, seg = idx & 7;
        const size_t g = gbase + (size_t)(jb * 64 + r) * HDIM + seg * 8;
        const uint32_t so = (r * ASTR + seg * 8) * 2;
        cp_async16(kvbase + so,                  g_Khi + g);
        cp_async16(kvbase + 64 * ASTR * 2 + so,  g_Klo + g);
        cp_async16(kvbase + 128 * ASTR * 2 + so, g_V + g);
    }
}

__device__ __forceinline__ void attn_load_q(uint32_t uQh, uint32_t uQl,
                                            size_t gbase, int qb, int tid)
{
#pragma unroll
    for (int i = 0; i < 4; ++i) {
        int idx = tid + i * 256;
        int r = idx >> 3, seg = idx & 7;
        const size_t g = gbase + (size_t)(qb * 128 + r) * HDIM + seg * 8;
        const uint32_t so = (r * ASTR + seg * 8) * 2;
        cp_async16(uQh + so, g_Qhi + g);
        cp_async16(uQl + so, g_Qlo + g);
    }
}

__global__ __launch_bounds__(256, 2) void attn_mma_kernel()
{
    extern __shared__ char smraw[];
    const uint32_t uQh  = smem_u32(smraw);
    const uint32_t uQl  = uQh + Q_BYTES;
    const uint32_t uKV0 = uQl + Q_BYTES;

    const int tid = threadIdx.x, wid = tid >> 5, lane = tid & 31;
    const int pp = blockIdx.x;               // 0..3 (pair index)
    const int bh = blockIdx.y;               // 0..63
    const size_t gbase = (size_t)bh * SEQ * HDIM;
    const int qa = 7 - pp;
    const int cb = 2 * qa + 2;               // tiles consumed by first q-tile

    attn_load_q(uQh, uQl, gbase, qa, tid);
    CP_COMMIT();
    cp_wait<0>();
    __syncthreads();                         // Q visible

    if (wid < 2) {
        attn_load_kv64(uKV0, gbase, 0, tid);
        CP_COMMIT();
        attn_load_kv64(uKV0 + KVBUF, gbase, 1, tid);
        CP_COMMIT();
        cp_wait<1>();                        // tile 0 complete
        BAR_ARRIVE(NBAR_F0, BARCNT);
    }

    float o[8][4];
#pragma unroll
    for (int nt = 0; nt < 8; ++nt)
#pragma unroll
        for (int e = 0; e < 4; ++e) o[nt][e] = 0.f;
    float m0 = -1e30f, m1 = -1e30f, l0 = 0.f, l1 = 0.f;

    int qb = qa;
    int r0g = qb * 128 + wid * 16 + (lane >> 2);

    const int a_row = lane & 15;
    const int a_koff = (lane >> 4) * 8;
    const int b_row = (lane & 7) + ((lane >> 4) * 8);
    const int b_koff = ((lane >> 3) & 1) * 8;

    for (int c = 0; c < ATTN_G; ++c) {
        if (c == cb) {
            const float i0 = 1.f / l0, i1 = 1.f / l1;
            const int r0 = wid * 16 + (lane >> 2);
            const size_t zr0 = ((size_t)bh * SEQ + (size_t)qb * 128 + r0) * HDIM;
#pragma unroll
            for (int nt = 0; nt < 8; ++nt) {
                const int cc = nt * 8 + (lane & 3) * 2;
                *(uint32_t*)(g_Z + zr0 + cc) = packh2(o[nt][0] * i0, o[nt][1] * i0);
                *(uint32_t*)(g_Z + zr0 + 8 * HDIM + cc) = packh2(o[nt][2] * i1, o[nt][3] * i1);
            }
#pragma unroll
            for (int nt = 0; nt < 8; ++nt)
#pragma unroll
                for (int e = 0; e < 4; ++e) o[nt][e] = 0.f;
            m0 = -1e30f; m1 = -1e30f; l0 = 0.f; l1 = 0.f;
            qb = pp;
            r0g = qb * 128 + wid * 16 + (lane >> 2);
            __syncthreads();
            attn_load_q(uQh, uQl, gbase, qb, tid);
            CP_COMMIT();
            cp_wait<0>();
            __syncthreads();
        }

        BAR_SYNC_N((c & 1) ? NBAR_F1 : NBAR_F0, BARCNT);
        const uint32_t kvb = uKV0 + (c & 1) * KVBUF;
        const uint32_t uKh = kvb;
        const uint32_t uKl = kvb + 64 * ASTR * 2;
        const uint32_t uVh = kvb + 128 * ASTR * 2;
        const int jb = (c < cb) ? c : c - cb;

        float s[8][4];
#pragma unroll
        for (int nt = 0; nt < 8; ++nt)
#pragma unroll
            for (int e = 0; e < 4; ++e) s[nt][e] = 0.f;

#pragma unroll
        for (int ks = 0; ks < 4; ++ks) {
            uint32_t qh[4], ql[4];
            {
                uint32_t off = ((wid * 16 + a_row) * ASTR + ks * 16 + a_koff) * 2;
                ldmatrix_x4(qh, uQh + off);
                ldmatrix_x4(ql, uQl + off);
            }
            uint32_t kh[4][4], kl[4][4];
#pragma unroll
            for (int g = 0; g < 4; ++g) {
                uint32_t off = ((g * 16 + b_row) * ASTR + ks * 16 + b_koff) * 2;
                ldmatrix_x4(kh[g], uKh + off);
                ldmatrix_x4(kl[g], uKl + off);
            }
#pragma unroll
            for (int g = 0; g < 4; ++g)
#pragma unroll
                for (int hh = 0; hh < 2; ++hh)
                    mma_16816(s[2 * g + hh], qh, kh[g][hh * 2], kh[g][hh * 2 + 1]);
#pragma unroll
            for (int g = 0; g < 4; ++g)
#pragma unroll
                for (int hh = 0; hh < 2; ++hh)
                    mma_16816(s[2 * g + hh], qh, kl[g][hh * 2], kl[g][hh * 2 + 1]);
#pragma unroll
            for (int g = 0; g < 4; ++g)
#pragma unroll
                for (int hh = 0; hh < 2; ++hh)
                    mma_16816(s[2 * g + hh], ql, kh[g][hh * 2], kh[g][hh * 2 + 1]);
        }

        const bool needmask = (jb >= 2 * qb);
        float mx0 = -1e30f, mx1 = -1e30f;
#pragma unroll
        for (int nt = 0; nt < 8; ++nt) {
            if (needmask) {
                const int cc = jb * 64 + nt * 8 + (lane & 3) * 2;
                s[nt][0] = (cc     <= r0g)     ? s[nt][0] : -1e30f;
                s[nt][1] = (cc + 1 <= r0g)     ? s[nt][1] : -1e30f;
                s[nt][2] = (cc     <= r0g + 8) ? s[nt][2] : -1e30f;
                s[nt][3] = (cc + 1 <= r0g + 8) ? s[nt][3] : -1e30f;
            }
            mx0 = fmaxf(mx0, fmaxf(s[nt][0], s[nt][1]));
            mx1 = fmaxf(mx1, fmaxf(s[nt][2], s[nt][3]));
        }
        mx0 = fmaxf(mx0, __shfl_xor_sync(0xffffffffu, mx0, 1));
        mx0 = fmaxf(mx0, __shfl_xor_sync(0xffffffffu, mx0, 2));
        mx1 = fmaxf(mx1, __shfl_xor_sync(0xffffffffu, mx1, 1));
        mx1 = fmaxf(mx1, __shfl_xor_sync(0xffffffffu, mx1, 2));

        const float nm0 = fmaxf(m0, mx0), nm1 = fmaxf(m1, mx1);
        const float al0 = exp2f(m0 - nm0), al1 = exp2f(m1 - nm1);
        m0 = nm0; m1 = nm1;

#pragma unroll
        for (int nt = 0; nt < 8; ++nt) {
            o[nt][0] *= al0; o[nt][1] *= al0;
            o[nt][2] *= al1; o[nt][3] *= al1;
        }

        float rs0 = 0.f, rs1 = 0.f;
#pragma unroll
        for (int ks = 0; ks < 4; ++ks) {
            float* sa = s[2 * ks];
            float* sb = s[2 * ks + 1];
            sa[0] = exp2f(sa[0] - m0);
            sa[1] = exp2f(sa[1] - m0);
            sa[2] = exp2f(sa[2] - m1);
            sa[3] = exp2f(sa[3] - m1);
            sb[0] = exp2f(sb[0] - m0);
            sb[1] = exp2f(sb[1] - m0);
            sb[2] = exp2f(sb[2] - m1);
            sb[3] = exp2f(sb[3] - m1);
            rs0 += sa[0] + sa[1] + sb[0] + sb[1];
            rs1 += sa[2] + sa[3] + sb[2] + sb[3];

            uint32_t ph[4];
            ph[0] = packh2(sa[0], sa[1]);
            ph[1] = packh2(sa[2], sa[3]);
            ph[2] = packh2(sb[0], sb[1]);
            ph[3] = packh2(sb[2], sb[3]);

            uint32_t vh[4][4];
#pragma unroll
            for (int dg = 0; dg < 4; ++dg) {
                uint32_t off = (((lane & 15) + ks * 16) * ASTR + dg * 16 + (lane >> 4) * 8) * 2;
                ldmatrix_x4_trans(vh[dg], uVh + off);
            }
#pragma unroll
            for (int dg = 0; dg < 4; ++dg)
#pragma unroll
                for (int hh = 0; hh < 2; ++hh)
                    mma_16816_f16(o[2 * dg + hh], ph, vh[dg][hh * 2], vh[dg][hh * 2 + 1]);
        }

        BAR_ARRIVE((c & 1) ? NBAR_E1 : NBAR_E0, BARCNT);

        if (wid < 2) {
            const bool refill = (c + 2 < ATTN_G);
            if (refill) {
                BAR_SYNC_N((c & 1) ? NBAR_E1 : NBAR_E0, BARCNT);
                const int g = c + 2;
                const int gj = (g < cb) ? g : g - cb;
                attn_load_kv64(uKV0 + (g & 1) * KVBUF, gbase, gj, tid);
                CP_COMMIT();
            }
            if (c + 1 < ATTN_G) {
                if (refill) cp_wait<1>();
                else        cp_wait<0>();
                BAR_ARRIVE(((c + 1) & 1) ? NBAR_F1 : NBAR_F0, BARCNT);
            }
        }

        rs0 += __shfl_xor_sync(0xffffffffu, rs0, 1);
        rs0 += __shfl_xor_sync(0xffffffffu, rs0, 2);
        rs1 += __shfl_xor_sync(0xffffffffu, rs1, 1);
        rs1 += __shfl_xor_sync(0xffffffffu, rs1, 2);
        l0 = l0 * al0 + rs0;
        l1 = l1 * al1 + rs1;
    }

    const float inv0 = 1.f / l0, inv1 = 1.f / l1;
    const int r0 = wid * 16 + (lane >> 2);
    const size_t zr0 = ((size_t)bh * SEQ + (size_t)qb * 128 + r0) * HDIM;
#pragma unroll
    for (int nt = 0; nt < 8; ++nt) {
        const int cc = nt * 8 + (lane & 3) * 2;
        *(uint32_t*)(g_Z + zr0 + cc) = packh2(o[nt][0] * inv0, o[nt][1] * inv0);
        *(uint32_t*)(g_Z + zr0 + 8 * HDIM + cc) = packh2(o[nt][2] * inv1, o[nt][3] * inv1);
    }
}

// ---------------- launch ----------------
extern "C" void kernel_launch(void* const* d_in, const int* in_sizes, int n_in,
                              void* d_out, int out_size)
{
    const float* X  = (const float*)d_in[0];
    const float* wq = (const float*)d_in[2];
    const float* bq = (const float*)d_in[3];
    const float* wk = (const float*)d_in[4];
    const float* bk = (const float*)d_in[5];
    const float* wv = (const float*)d_in[6];
    const float* bv = (const float*)d_in[7];
    const float* wo = (const float*)d_in[8];
    const float* bo = (const float*)d_in[9];
    float* out = (float*)d_out;

    __nv_bfloat16 *Xhi, *Xlo;
    __half *Xh;
    cudaGetSymbolAddress((void**)&Xhi, g_Xhi);
    cudaGetSymbolAddress((void**)&Xlo, g_Xlo);
    cudaGetSymbolAddress((void**)&Xh,  g_Xh);

    cudaFuncSetAttribute(attn_mma_kernel, cudaFuncAttributeMaxDynamicSharedMemorySize, ATTN_SMEM);
    cudaFuncSetAttribute(qk_mma_kernel,  cudaFuncAttributeMaxDynamicSharedMemorySize, GEMM_SMEM);
    cudaFuncSetAttribute(v_mma_kernel,   cudaFuncAttributeMaxDynamicSharedMemorySize, HGEMM_SMEM);
    cudaFuncSetAttribute(out_mma_kernel, cudaFuncAttributeMaxDynamicSharedMemorySize, HGEMM_SMEM);

    // split X into bf16 hi/lo + fp16 single; split+transpose weights
    cvt_split_kernel<<<(MROWS * EMB / 4) / 256, 256>>>(X, Xhi, Xlo, Xh);
    cvt_splitT_kernel<<<dim3(EMB / 32, EMB / 32, 4), 256>>>(wq, wk, wv, wo);

    // Q/K projections: bf16 3-term (z: 0=Q(xQSCALE) 1=K), per-head layout
    qk_mma_kernel<<<dim3(EMB / 128, MROWS / 128, 2), 256, GEMM_SMEM>>>(bq, bk);
    // V projection: fp16 single-term -> V single fp16, per-head layout
    v_mma_kernel<<<dim3(EMB / 128, MROWS / 128), 256, HGEMM_SMEM>>>(bv);

    // causal flash attention (PV single-term) -> g_Z (fp16)
    attn_mma_kernel<<<dim3(4, BATCH * HEADS), 256, ATTN_SMEM>>>();

    // output projection: fp16 single-term
    out_mma_kernel<<<dim3(EMB / 128, MROWS / 128), 256, HGEMM_SMEM>>>(bo, out);

    (void)in_sizes; (void)n_in; (void)out_size;
}